// round 14
// baseline (speedup 1.0000x reference)
#include <cuda_runtime.h>
#include <cuda_bf16.h>
#include <math.h>
#include <cstdint>

#define HID 1024
#define BATCH 2
#define TLEN 4096
#define NHEAD 8
#define DKK 128
#define DVV 128
#define NCHUNK 64
#define CHUNKSZ 64
#define MROWS (BATCH*TLEN)          /* 8192 */
#define FMROWS (BATCH*TLEN*NHEAD)   /* 65536 */
#define HH (HID*HID)

#define SCALE 0.08838834764831845f  /* 128^-0.5 */

// ---------------- scratch ----------------------------------------------------
__device__ float g_qb[MROWS*HID];
__device__ float g_kb[MROWS*HID];
__device__ float g_vb[MROWS*HID];
__device__ float g_qc[MROWS*HID];   /* reused as bf16 hi/lo pair for q conv out */
__device__ float g_kc[MROWS*HID];   /* reused as bf16 hi/lo pair for k conv out */
__device__ float g_vc[MROWS*HID];
__device__ float g_qf[MROWS*HID];
__device__ float g_kf[MROWS*HID];
__device__ float g_o [MROWS*HID];
__device__ float g_kv[(size_t)BATCH*NHEAD*NCHUNK*DKK*DVV];
__device__ __nv_bfloat16 g_xh[MROWS*HID];
__device__ __nv_bfloat16 g_xl[MROWS*HID];
__device__ __nv_bfloat16 g_wh[4*HH];
__device__ __nv_bfloat16 g_wl[4*HH];
__device__ __nv_bfloat16 g_oh[MROWS*HID];
__device__ __nv_bfloat16 g_ol[MROWS*HID];
__device__ __nv_bfloat16 g_fwh[4*DKK*DKK];
__device__ __nv_bfloat16 g_fwl[4*DKK*DKK];

// ---------------- PTX helpers ------------------------------------------------
__device__ __forceinline__ uint32_t smem_to_u32(const void* p) {
    uint32_t a;
    asm("{ .reg .u64 t; cvta.to.shared.u64 t, %1; cvt.u32.u64 %0, t; }" : "=r"(a) : "l"(p));
    return a;
}
__device__ __forceinline__ void cp_async16(uint32_t dst, const void* src) {
    asm volatile("cp.async.cg.shared.global [%0], [%1], 16;" :: "r"(dst), "l"(src));
}
#define CP_COMMIT() asm volatile("cp.async.commit_group;" ::: "memory")
#define CP_WAIT1()  asm volatile("cp.async.wait_group 1;" ::: "memory")
#define CP_WAIT0()  asm volatile("cp.async.wait_group 0;" ::: "memory")

__device__ __forceinline__ void ldmx4(uint32_t* r, uint32_t addr) {
    asm volatile("ldmatrix.sync.aligned.m8n8.x4.shared.b16 {%0,%1,%2,%3}, [%4];"
        : "=r"(r[0]), "=r"(r[1]), "=r"(r[2]), "=r"(r[3]) : "r"(addr));
}
__device__ __forceinline__ void mma16816(float* d, const uint32_t* a, const uint32_t* b) {
    asm volatile(
        "mma.sync.aligned.m16n8k16.row.col.f32.bf16.bf16.f32 "
        "{%0,%1,%2,%3}, {%4,%5,%6,%7}, {%8,%9}, {%0,%1,%2,%3};"
        : "+f"(d[0]), "+f"(d[1]), "+f"(d[2]), "+f"(d[3])
        : "r"(a[0]), "r"(a[1]), "r"(a[2]), "r"(a[3]), "r"(b[0]), "r"(b[1]));
}

__device__ __forceinline__ void bsplit4a(float4 v, __nv_bfloat16* h, __nv_bfloat16* l) {
    h[0] = __float2bfloat16(v.x); l[0] = __float2bfloat16(v.x - __bfloat162float(h[0]));
    h[1] = __float2bfloat16(v.y); l[1] = __float2bfloat16(v.y - __bfloat162float(h[1]));
    h[2] = __float2bfloat16(v.z); l[2] = __float2bfloat16(v.z - __bfloat162float(h[2]));
    h[3] = __float2bfloat16(v.w); l[3] = __float2bfloat16(v.w - __bfloat162float(h[3]));
}
__device__ __forceinline__ uint32_t pack2(__nv_bfloat16 a, __nv_bfloat16 b) {
    return ((uint32_t)__bfloat16_as_ushort(b) << 16) | __bfloat16_as_ushort(a);
}
__device__ __forceinline__ void bsplit4(float4 v, uint2& hu, uint2& lu) {
    __nv_bfloat16 h[4], l[4];
    bsplit4a(v, h, l);
    hu.x = pack2(h[0], h[1]); hu.y = pack2(h[2], h[3]);
    lu.x = pack2(l[0], l[1]); lu.y = pack2(l[2], l[3]);
}

// ---------------- fp32 -> bf16 hi/lo converters -------------------------------
__global__ void split_kernel(const float* __restrict__ X,
                             __nv_bfloat16* __restrict__ H,
                             __nv_bfloat16* __restrict__ L, int n4)
{
    int i = blockIdx.x * blockDim.x + threadIdx.x;
    if (i >= n4) return;
    float4 v = reinterpret_cast<const float4*>(X)[i];
    uint2 hu, lu;
    bsplit4(v, hu, lu);
    reinterpret_cast<uint2*>(H)[i] = hu;
    reinterpret_cast<uint2*>(L)[i] = lu;
}

__global__ void split_w_kernel(const float* __restrict__ W0, const float* __restrict__ W1,
                               const float* __restrict__ W2, const float* __restrict__ W3,
                               __nv_bfloat16* __restrict__ H, __nv_bfloat16* __restrict__ L)
{
    int z = blockIdx.y;
    const float* W = z == 0 ? W0 : (z == 1 ? W1 : (z == 2 ? W2 : W3));
    int i = blockIdx.x * blockDim.x + threadIdx.x;
    float4 v = reinterpret_cast<const float4*>(W)[i];
    uint2 hu, lu;
    bsplit4(v, hu, lu);
    size_t o = (size_t)z * (HH / 4) + i;
    reinterpret_cast<uint2*>(H)[o] = hu;
    reinterpret_cast<uint2*>(L)[o] = lu;
}

__global__ void split_fmw_kernel(const float* __restrict__ Q1, const float* __restrict__ Q2,
                                 const float* __restrict__ K1, const float* __restrict__ K2,
                                 __nv_bfloat16* __restrict__ FH, __nv_bfloat16* __restrict__ FL)
{
    int z = blockIdx.y;
    const float* W = z == 0 ? Q1 : (z == 1 ? Q2 : (z == 2 ? K1 : K2));
    int i = blockIdx.x * blockDim.x + threadIdx.x;
    float4 v = reinterpret_cast<const float4*>(W)[i];
    uint2 hu, lu;
    bsplit4(v, hu, lu);
    reinterpret_cast<uint2*>(FH)[z * 4096 + i] = hu;
    reinterpret_cast<uint2*>(FL)[z * 4096 + i] = lu;
}

// ---------------- HMMA bf16 3-pass GEMM body (512 threads, 16 warps) ---------
// 5-buffer cp.async pipeline, ONE barrier per 2 stages, fragment ping-pong.
#define ROWB 80
#define ARRB (128*ROWB)        /* 10240 */
#define BUFB (4*ARRB)          /* Ah,Al,Bh,Bl = 40960 */
#define GEMM_SMEM (5*BUFB)     /* 204800 */

struct Frag {
    uint32_t rah[2][4], ral[2][4];
    uint32_t rbh[4][2], rbl[4][2];
};

__device__ __forceinline__ void load_frag(Frag& f, uint32_t bb, int ks,
                                          int a_row, int a_kc, int b_row, int b_kc)
{
#pragma unroll
    for (int mt = 0; mt < 2; ++mt) {
        uint32_t ad = bb + (a_row + mt * 16) * ROWB + (a_kc + ks * 16) * 2;
        ldmx4(f.rah[mt], ad);
        ldmx4(f.ral[mt], ad + ARRB);
    }
#pragma unroll
    for (int np = 0; np < 2; ++np) {
        uint32_t bd = bb + 2 * ARRB + (b_row + np * 16) * ROWB + (b_kc + ks * 16) * 2;
        uint32_t t[4];
        ldmx4(t, bd);
        f.rbh[np*2][0] = t[0]; f.rbh[np*2][1] = t[1];
        f.rbh[np*2+1][0] = t[2]; f.rbh[np*2+1][1] = t[3];
        ldmx4(t, bd + ARRB);
        f.rbl[np*2][0] = t[0]; f.rbl[np*2][1] = t[1];
        f.rbl[np*2+1][0] = t[2]; f.rbl[np*2+1][1] = t[3];
    }
}

__device__ __forceinline__ void mma_frag(float acc[2][4][4], const Frag& f)
{
#pragma unroll
    for (int mt = 0; mt < 2; ++mt)
#pragma unroll
        for (int nt = 0; nt < 4; ++nt)
            mma16816(acc[mt][nt], f.rah[mt], f.rbh[nt]);
#pragma unroll
    for (int mt = 0; mt < 2; ++mt)
#pragma unroll
        for (int nt = 0; nt < 4; ++nt)
            mma16816(acc[mt][nt], f.rah[mt], f.rbl[nt]);
#pragma unroll
    for (int mt = 0; mt < 2; ++mt)
#pragma unroll
        for (int nt = 0; nt < 4; ++nt)
            mma16816(acc[mt][nt], f.ral[mt], f.rbh[nt]);
}

__device__ __forceinline__ void gemm3_body(
    const __nv_bfloat16* __restrict__ Ah, const __nv_bfloat16* __restrict__ Al,
    const __nv_bfloat16* __restrict__ Bh, const __nv_bfloat16* __restrict__ Bl,
    float* __restrict__ C, int N, int K, char* smem)
{
    uint32_t sb = smem_to_u32(smem);
    int tid = threadIdx.x, wid = tid >> 5, lane = tid & 31;
    int m0 = blockIdx.y * 128, n0 = blockIdx.x * 128;
    int warp_m = (wid & 3) * 32, warp_n = (wid >> 2) * 32;
    const int NST = K / 32;   /* 32, even */

    float acc[2][4][4];
#pragma unroll
    for (int i = 0; i < 2; ++i)
#pragma unroll
        for (int j = 0; j < 4; ++j)
#pragma unroll
            for (int r = 0; r < 4; ++r) acc[i][j][r] = 0.f;

#define PREFETCH(s) do { \
        int _k0 = (s) * 32; \
        uint32_t _bb = sb + ((s) % 5) * BUFB; \
        int _row = tid >> 2, _ch = tid & 3; \
        uint32_t _off = _row * ROWB + _ch * 16; \
        size_t _ga = (size_t)(m0 + _row) * K + _k0 + _ch * 8; \
        size_t _gb = (size_t)(n0 + _row) * K + _k0 + _ch * 8; \
        cp_async16(_bb + _off,          Ah + _ga); \
        cp_async16(_bb + ARRB + _off,   Al + _ga); \
        cp_async16(_bb + 2*ARRB + _off, Bh + _gb); \
        cp_async16(_bb + 3*ARRB + _off, Bl + _gb); \
    } while (0)

    PREFETCH(0); CP_COMMIT();
    PREFETCH(1); CP_COMMIT();
    PREFETCH(2); CP_COMMIT();

    int a_row = warp_m + (lane & 15);
    int a_kc  = (lane >> 4) * 8;
    int bg    = lane >> 3;
    int b_row = warp_n + ((bg >> 1) * 8) + (lane & 7);
    int b_kc  = (bg & 1) * 8;

    Frag f0, f1;

    for (int s = 0; s < NST; s += 2) {
        // stages <= s+1 complete (own thread)
        if (s + 3 < NST) CP_WAIT1(); else CP_WAIT0();
        __syncthreads();      // visibility of stages s,s+1 + everyone done <= s-1

        // safe: bufs (s+3)%5=(s-2)%5 and (s+4)%5=(s-1)%5 drained by all
        if (s + 3 < NST) { PREFETCH(s + 3); CP_COMMIT(); }
        if (s + 4 < NST) { PREFETCH(s + 4); CP_COMMIT(); }

        uint32_t bb0 = sb + ((s)     % 5) * BUFB;
        uint32_t bb1 = sb + ((s + 1) % 5) * BUFB;
        load_frag(f0, bb0, 0, a_row, a_kc, b_row, b_kc);
        load_frag(f1, bb0, 1, a_row, a_kc, b_row, b_kc);
        mma_frag(acc, f0);
        load_frag(f0, bb1, 0, a_row, a_kc, b_row, b_kc);
        mma_frag(acc, f1);
        load_frag(f1, bb1, 1, a_row, a_kc, b_row, b_kc);
        mma_frag(acc, f0);
        mma_frag(acc, f1);
    }
#undef PREFETCH

    int cr = lane >> 2, cc = (lane & 3) * 2;
#pragma unroll
    for (int mt = 0; mt < 2; ++mt)
#pragma unroll
        for (int nt = 0; nt < 4; ++nt) {
            int row = m0 + warp_m + mt * 16 + cr;
            int col = n0 + warp_n + nt * 8 + cc;
            *reinterpret_cast<float2*>(&C[(size_t)row * N + col]) =
                make_float2(acc[mt][nt][0], acc[mt][nt][1]);
            *reinterpret_cast<float2*>(&C[(size_t)(row + 8) * N + col]) =
                make_float2(acc[mt][nt][2], acc[mt][nt][3]);
        }
}

__global__ __launch_bounds__(512, 1)
void hmma_gemm_qkv(const __nv_bfloat16* __restrict__ Xh, const __nv_bfloat16* __restrict__ Xl,
                   const __nv_bfloat16* __restrict__ Wh, const __nv_bfloat16* __restrict__ Wl,
                   float* __restrict__ Cq, float* __restrict__ Ck, float* __restrict__ Cv)
{
    extern __shared__ char smem[];
    int z = blockIdx.z;
    const __nv_bfloat16* Bh = Wh + (size_t)z * HH;
    const __nv_bfloat16* Bl = Wl + (size_t)z * HH;
    float* C = z == 0 ? Cq : (z == 1 ? Ck : Cv);
    gemm3_body(Xh, Xl, Bh, Bl, C, HID, HID, smem);
}

__global__ __launch_bounds__(512, 1)
void hmma_gemm_wo(const __nv_bfloat16* __restrict__ Ah, const __nv_bfloat16* __restrict__ Al,
                  const __nv_bfloat16* __restrict__ Bh, const __nv_bfloat16* __restrict__ Bl,
                  float* __restrict__ C)
{
    extern __shared__ char smem[];
    gemm3_body(Ah, Al, Bh, Bl, C, HID, HID, smem);
}

// ---------------- causal depthwise conv1d (K=4) + SiLU, merged, 4 t/thread ---
// q/k outputs (z=0,1) are written as bf16 hi/lo (fm's only input);
// v output (z=2) stays fp32 for attention.
__global__ void conv_silu4_kernel(const float* __restrict__ X0, const float* __restrict__ W0,
                                  __nv_bfloat16* __restrict__ Y0h, __nv_bfloat16* __restrict__ Y0l,
                                  const float* __restrict__ X1, const float* __restrict__ W1,
                                  __nv_bfloat16* __restrict__ Y1h, __nv_bfloat16* __restrict__ Y1l,
                                  const float* __restrict__ X2, const float* __restrict__ W2,
                                  float* __restrict__ Y2)
{
    int z = blockIdx.y;
    const float* X = z == 0 ? X0 : (z == 1 ? X1 : X2);
    const float* W = z == 0 ? W0 : (z == 1 ? W1 : W2);

    int idx = blockIdx.x * blockDim.x + threadIdx.x;
    int d = idx & (HID - 1);
    int tq = idx >> 10;
    int t0 = (tq & (TLEN / 4 - 1)) * 4;
    size_t row0 = (size_t)tq * 4;
    const float* xp = X + row0 * HID + d;
    float4 wv = *reinterpret_cast<const float4*>(&W[d * 4]);
    float xv[7];
#pragma unroll
    for (int o = 0; o < 7; ++o) {
        int t = t0 + o - 3;
        xv[o] = (t >= 0) ? xp[(ptrdiff_t)(o - 3) * HID] : 0.f;
    }
    if (z == 2) {
#pragma unroll
        for (int j = 0; j < 4; ++j) {
            float s = wv.x * xv[j] + wv.y * xv[j + 1] + wv.z * xv[j + 2] + wv.w * xv[j + 3];
            Y2[(row0 + j) * HID + d] = s / (1.f + expf(-s));
        }
    } else {
        __nv_bfloat16* YH = z == 0 ? Y0h : Y1h;
        __nv_bfloat16* YL = z == 0 ? Y0l : Y1l;
#pragma unroll
        for (int j = 0; j < 4; ++j) {
            float s = wv.x * xv[j] + wv.y * xv[j + 1] + wv.z * xv[j + 2] + wv.w * xv[j + 3];
            float y = s / (1.f + expf(-s));
            __nv_bfloat16 h = __float2bfloat16(y);
            __nv_bfloat16 l = __float2bfloat16(y - __bfloat162float(h));
            YH[(row0 + j) * HID + d] = h;
            YL[(row0 + j) * HID + d] = l;
        }
    }
}

// ---------------- hadamard feature map via HMMA bf16 3-pass (merged q/k) -----
// A arrives presplit bf16 hi/lo (from conv); weights presplit too.
#define FROWB 272
#define FSZ (128*FROWB)          /* 34816 per array */
#define FM_SMEM (6*FSZ)          /* 208896 */

__global__ __launch_bounds__(256, 1)
void fm_hmma3_kernel(const __nv_bfloat16* __restrict__ AqH, const __nv_bfloat16* __restrict__ AqL,
                     const __nv_bfloat16* __restrict__ AkH, const __nv_bfloat16* __restrict__ AkL,
                     const __nv_bfloat16* __restrict__ FH, const __nv_bfloat16* __restrict__ FL,
                     const float* __restrict__ Bq1, const float* __restrict__ Bq2,
                     const float* __restrict__ Bk1, const float* __restrict__ Bk2,
                     float* __restrict__ Yq, float* __restrict__ Yk)
{
    extern __shared__ char smem[];
    int z = blockIdx.y;
    const __nv_bfloat16* AH = z ? AkH : AqH;
    const __nv_bfloat16* AL = z ? AkL : AqL;
    const float* B1 = z ? Bk1 : Bq1;
    const float* B2 = z ? Bk2 : Bq2;
    float* Y        = z ? Yk  : Yq;
    const __nv_bfloat16* W1h = FH + (size_t)(z * 2)     * 16384;
    const __nv_bfloat16* W1l = FL + (size_t)(z * 2)     * 16384;
    const __nv_bfloat16* W2h = FH + (size_t)(z * 2 + 1) * 16384;
    const __nv_bfloat16* W2l = FL + (size_t)(z * 2 + 1) * 16384;

    uint32_t sb = smem_to_u32(smem);
    uint32_t sAh = sb, sAl = sb + FSZ;
    uint32_t sW1h = sb + 2 * FSZ, sW1l = sb + 3 * FSZ;
    uint32_t sW2h = sb + 4 * FSZ, sW2l = sb + 5 * FSZ;
    int tid = threadIdx.x, wid = tid >> 5, lane = tid & 31;
    int m0 = blockIdx.x * 128;
    int warp_m = (wid & 3) * 32, warp_n = (wid >> 2) * 64;

    // stage A hi/lo via direct uint4 copies (presplit by conv)
#pragma unroll
    for (int it = 0; it < 8; ++it) {
        int idx = tid + it * 256;
        int m = idx >> 4, c16 = idx & 15;
        uint32_t off = m * FROWB + c16 * 16;
        size_t gsrc = (size_t)(m0 + m) * 16 + c16;   // uint4 index into [.,128] bf16
        *reinterpret_cast<uint4*>(smem + off)       = reinterpret_cast<const uint4*>(AH)[gsrc];
        *reinterpret_cast<uint4*>(smem + FSZ + off) = reinterpret_cast<const uint4*>(AL)[gsrc];
    }
    // stage presplit weights via direct uint4 copies
#pragma unroll
    for (int it = 0; it < 8; ++it) {
        int idx = tid + it * 256;
        int e = idx >> 4, c16 = idx & 15;
        uint32_t off = e * FROWB + c16 * 16;
        *reinterpret_cast<uint4*>(smem + 2 * FSZ + off) = reinterpret_cast<const uint4*>(W1h)[idx];
        *reinterpret_cast<uint4*>(smem + 3 * FSZ + off) = reinterpret_cast<const uint4*>(W1l)[idx];
        *reinterpret_cast<uint4*>(smem + 4 * FSZ + off) = reinterpret_cast<const uint4*>(W2h)[idx];
        *reinterpret_cast<uint4*>(smem + 5 * FSZ + off) = reinterpret_cast<const uint4*>(W2l)[idx];
    }
    __syncthreads();

    int a_row = warp_m + (lane & 15);
    int a_kc  = (lane >> 4) * 8;
    int bg    = lane >> 3;
    int b_row = ((bg >> 1) * 8) + (lane & 7);
    int b_kc  = (bg & 1) * 8;
    int cr = lane >> 2, cc = (lane & 3) * 2;

#pragma unroll
    for (int nh = 0; nh < 2; ++nh) {
        float acc1[2][4][4], acc2[2][4][4];
#pragma unroll
        for (int i = 0; i < 2; ++i)
#pragma unroll
            for (int j = 0; j < 4; ++j)
#pragma unroll
                for (int r = 0; r < 4; ++r) { acc1[i][j][r] = 0.f; acc2[i][j][r] = 0.f; }

#pragma unroll
        for (int ks = 0; ks < 8; ++ks) {
            uint32_t rah[2][4], ral[2][4];
#pragma unroll
            for (int mt = 0; mt < 2; ++mt) {
                uint32_t ad = (a_row + mt * 16) * FROWB + (a_kc + ks * 16) * 2;
                ldmx4(rah[mt], sAh + ad);
                ldmx4(ral[mt], sAl + ad);
            }
            uint32_t rb1h[4][2], rb1l[4][2], rb2h[4][2], rb2l[4][2];
#pragma unroll
            for (int np = 0; np < 2; ++np) {
                uint32_t roff = (warp_n + nh * 32 + np * 16 + b_row) * FROWB + (b_kc + ks * 16) * 2;
                uint32_t t[4];
                ldmx4(t, sW1h + roff);
                rb1h[np*2][0] = t[0]; rb1h[np*2][1] = t[1];
                rb1h[np*2+1][0] = t[2]; rb1h[np*2+1][1] = t[3];
                ldmx4(t, sW1l + roff);
                rb1l[np*2][0] = t[0]; rb1l[np*2][1] = t[1];
                rb1l[np*2+1][0] = t[2]; rb1l[np*2+1][1] = t[3];
                ldmx4(t, sW2h + roff);
                rb2h[np*2][0] = t[0]; rb2h[np*2][1] = t[1];
                rb2h[np*2+1][0] = t[2]; rb2h[np*2+1][1] = t[3];
                ldmx4(t, sW2l + roff);
                rb2l[np*2][0] = t[0]; rb2l[np*2][1] = t[1];
                rb2l[np*2+1][0] = t[2]; rb2l[np*2+1][1] = t[3];
            }
#pragma unroll
            for (int mt = 0; mt < 2; ++mt)
#pragma unroll
                for (int nt = 0; nt < 4; ++nt) mma16816(acc1[mt][nt], rah[mt], rb1h[nt]);
#pragma unroll
            for (int mt = 0; mt < 2; ++mt)
#pragma unroll
                for (int nt = 0; nt < 4; ++nt) mma16816(acc2[mt][nt], rah[mt], rb2h[nt]);
#pragma unroll
            for (int mt = 0; mt < 2; ++mt)
#pragma unroll
                for (int nt = 0; nt < 4; ++nt) mma16816(acc1[mt][nt], ral[mt], rb1h[nt]);
#pragma unroll
            for (int mt = 0; mt < 2; ++mt)
#pragma unroll
                for (int nt = 0; nt < 4; ++nt) mma16816(acc2[mt][nt], ral[mt], rb2h[nt]);
#pragma unroll
            for (int mt = 0; mt < 2; ++mt)
#pragma unroll
                for (int nt = 0; nt < 4; ++nt) mma16816(acc1[mt][nt], rah[mt], rb1l[nt]);
#pragma unroll
            for (int mt = 0; mt < 2; ++mt)
#pragma unroll
                for (int nt = 0; nt < 4; ++nt) mma16816(acc2[mt][nt], rah[mt], rb2l[nt]);
        }

#pragma unroll
        for (int mt = 0; mt < 2; ++mt)
#pragma unroll
            for (int nt = 0; nt < 4; ++nt) {
                int col = warp_n + nh * 32 + nt * 8 + cc;
                float b1v0 = B1[col], b1v1 = B1[col + 1];
                float b2v0 = B2[col], b2v1 = B2[col + 1];
                int row0 = m0 + warp_m + mt * 16 + cr;
                float y0 = (acc1[mt][nt][0] + b1v0) * (acc2[mt][nt][0] + b2v0);
                float y1 = (acc1[mt][nt][1] + b1v1) * (acc2[mt][nt][1] + b2v1);
                float y2 = (acc1[mt][nt][2] + b1v0) * (acc2[mt][nt][2] + b2v0);
                float y3 = (acc1[mt][nt][3] + b1v1) * (acc2[mt][nt][3] + b2v1);
                *reinterpret_cast<float2*>(&Y[(size_t)row0 * 128 + col])       = make_float2(y0, y1);
                *reinterpret_cast<float2*>(&Y[(size_t)(row0 + 8) * 128 + col]) = make_float2(y2, y3);
            }
    }
}

// ---------------- phase A: intra-chunk attention + KV via HMMA bf16 3-pass ---
#define AQROW 272
#define ATROW 144
#define A_oQh 0
#define A_oQl 17408
#define A_oKh 34816
#define A_oKl 52224
#define A_oKTh 69632
#define A_oKTl 88064
#define A_oVTh 106496
#define A_oVTl 124928
#define A_oSh  143360
#define A_oSl  152576
#define ATTN_INTRA_SMEM 161792

__global__ __launch_bounds__(256, 1)
void attn_intra_hmma(const float* __restrict__ Q,
                     const float* __restrict__ Kf,
                     const float* __restrict__ V,
                     float* __restrict__ O,
                     float* __restrict__ KVb)
{
    extern __shared__ char sm[];
    uint32_t sb = smem_to_u32(sm);
    int c = blockIdx.x, bh = blockIdx.y;
    int b = bh >> 3, h = bh & 7;
    int t0 = c * CHUNKSZ;
    int tid = threadIdx.x, wid = tid >> 5, lane = tid & 31;

#pragma unroll
    for (int it = 0; it < 8; ++it) {
        int idx = tid + it * 256;
        int m = idx & 63, d4 = idx >> 6;
        size_t g = ((size_t)((b * TLEN + t0 + m) * NHEAD) + h) * DKK + d4 * 4;
        __nv_bfloat16 hh[4], ll[4];

        float4 vq = *reinterpret_cast<const float4*>(Q + g);
        vq.x *= SCALE; vq.y *= SCALE; vq.z *= SCALE; vq.w *= SCALE;
        bsplit4a(vq, hh, ll);
        *reinterpret_cast<uint32_t*>(sm + A_oQh + m * AQROW + d4 * 8)     = pack2(hh[0], hh[1]);
        *reinterpret_cast<uint32_t*>(sm + A_oQh + m * AQROW + d4 * 8 + 4) = pack2(hh[2], hh[3]);
        *reinterpret_cast<uint32_t*>(sm + A_oQl + m * AQROW + d4 * 8)     = pack2(ll[0], ll[1]);
        *reinterpret_cast<uint32_t*>(sm + A_oQl + m * AQROW + d4 * 8 + 4) = pack2(ll[2], ll[3]);

        float4 vk = *reinterpret_cast<const float4*>(Kf + g);
        bsplit4a(vk, hh, ll);
        *reinterpret_cast<uint32_t*>(sm + A_oKh + m * AQROW + d4 * 8)     = pack2(hh[0], hh[1]);
        *reinterpret_cast<uint32_t*>(sm + A_oKh + m * AQROW + d4 * 8 + 4) = pack2(hh[2], hh[3]);
        *reinterpret_cast<uint32_t*>(sm + A_oKl + m * AQROW + d4 * 8)     = pack2(ll[0], ll[1]);
        *reinterpret_cast<uint32_t*>(sm + A_oKl + m * AQROW + d4 * 8 + 4) = pack2(ll[2], ll[3]);
#pragma unroll
        for (int j = 0; j < 4; ++j) {
            int d = d4 * 4 + j;
            *reinterpret_cast<__nv_bfloat16*>(sm + A_oKTh + d * ATROW + m * 2) = hh[j];
            *reinterpret_cast<__nv_bfloat16*>(sm + A_oKTl + d * ATROW + m * 2) = ll[j];
        }

        float4 vv = *reinterpret_cast<const float4*>(V + g);
        bsplit4a(vv, hh, ll);
#pragma unroll
        for (int j = 0; j < 4; ++j) {
            int d = d4 * 4 + j;
            *reinterpret_cast<__nv_bfloat16*>(sm + A_oVTh + d * ATROW + m * 2) = hh[j];
            *reinterpret_cast<__nv_bfloat16*>(sm + A_oVTl + d * ATROW + m * 2) = ll[j];
        }
    }
    __syncthreads();

    int bg = lane >> 3;
    int cr = lane >> 2, cc = (lane & 3) * 2;

    // ---- (a) S = (q*scale) k^T, masked, stored hi/lo ----
    {
        int wm = (wid & 3) * 16, wn = (wid >> 2) * 32;
        float accS[4][4];
#pragma unroll
        for (int j = 0; j < 4; ++j)
#pragma unroll
            for (int r = 0; r < 4; ++r) accS[j][r] = 0.f;

        uint32_t aAddr = sb + (wm + (lane & 15)) * AQROW + (lane >> 4) * 16;
        uint32_t bAddr = sb + (wn + ((bg >> 1) * 8) + (lane & 7)) * AQROW + (bg & 1) * 16;
#pragma unroll
        for (int ks = 0; ks < 8; ++ks) {
            uint32_t rah[4], ral[4];
            ldmx4(rah, aAddr + A_oQh + ks * 32);
            ldmx4(ral, aAddr + A_oQl + ks * 32);
            uint32_t rbh[4][2], rbl[4][2];
#pragma unroll
            for (int np = 0; np < 2; ++np) {
                uint32_t t[4];
                ldmx4(t, bAddr + A_oKh + np * 16 * AQROW + ks * 32);
                rbh[np*2][0] = t[0]; rbh[np*2][1] = t[1];
                rbh[np*2+1][0] = t[2]; rbh[np*2+1][1] = t[3];
                ldmx4(t, bAddr + A_oKl + np * 16 * AQROW + ks * 32);
                rbl[np*2][0] = t[0]; rbl[np*2][1] = t[1];
                rbl[np*2+1][0] = t[2]; rbl[np*2+1][1] = t[3];
            }
#pragma unroll
            for (int nt = 0; nt < 4; ++nt) mma16816(accS[nt], rah, rbh[nt]);
#pragma unroll
            for (int nt = 0; nt < 4; ++nt) mma16816(accS[nt], rah, rbl[nt]);
#pragma unroll
            for (int nt = 0; nt < 4; ++nt) mma16816(accS[nt], ral, rbh[nt]);
        }
        int r0 = wm + cr;
#pragma unroll
        for (int nt = 0; nt < 4; ++nt) {
            int c0 = wn + nt * 8 + cc;
            float v00 = (c0     <= r0    ) ? accS[nt][0] : 0.f;
            float v01 = (c0 + 1 <= r0    ) ? accS[nt][1] : 0.f;
            float v10 = (c0     <= r0 + 8) ? accS[nt][2] : 0.f;
            float v11 = (c0 + 1 <= r0 + 8) ? accS[nt][3] : 0.f;
            __nv_bfloat16 h00 = __float2bfloat16(v00), h01 = __float2bfloat16(v01);
            __nv_bfloat16 h10 = __float2bfloat16(v10), h11 = __float2bfloat16(v11);
            __nv_bfloat16 l00 = __float2bfloat16(v00 - __bfloat162float(h00));
            __nv_bfloat16 l01 = __float2bfloat16(v01 - __bfloat162float(h01));
            __nv_bfloat16 l10 = __float2bfloat16(v10 - __bfloat162float(h10));
            __nv_bfloat16 l11 = __float2bfloat16(v11 - __bfloat162float(h11));
            *reinterpret_cast<uint32_t*>(sm + A_oSh + r0 * ATROW + c0 * 2)       = pack2(h00, h01);
            *reinterpret_cast<uint32_t*>(sm + A_oSl + r0 * ATROW + c0 * 2)       = pack2(l00, l01);
            *reinterpret_cast<uint32_t*>(sm + A_oSh + (r0 + 8) * ATROW + c0 * 2) = pack2(h10, h11);
            *reinterpret_cast<uint32_t*>(sm + A_oSl + (r0 + 8) * ATROW + c0 * 2) = pack2(l10, l11);
        }
    }

    // ---- (c) KV = k^T v ----
    {
        int wm = (wid & 3) * 32, wn = (wid >> 2) * 64;
        float acc[2][8][4];
#pragma unroll
        for (int i = 0; i < 2; ++i)
#pragma unroll
            for (int j = 0; j < 8; ++j)
#pragma unroll
                for (int r = 0; r < 4; ++r) acc[i][j][r] = 0.f;

        uint32_t aBase = sb + (wm + (lane & 15)) * ATROW + (lane >> 4) * 16;
        uint32_t bBase = sb + (wn + ((bg >> 1) * 8) + (lane & 7)) * ATROW + (bg & 1) * 16;
#pragma unroll
        for (int ks = 0; ks < 4; ++ks) {
            uint32_t rah[2][4], ral[2][4];
#pragma unroll
            for (int mt = 0; mt < 2; ++mt) {
                ldmx4(rah[mt], aBase + A_oKTh + mt * 16 * ATROW + ks * 32);
                ldmx4(ral[mt], aBase + A_oKTl + mt * 16 * ATROW + ks * 32);
            }
            uint32_t rbh[8][2], rbl[8][2];
#pragma unroll
            for (int np = 0; np < 4; ++np) {
                uint32_t t[4];
                ldmx4(t, bBase + A_oVTh + np * 16 * ATROW + ks * 32);
                rbh[np*2][0] = t[0]; rbh[np*2][1] = t[1];
                rbh[np*2+1][0] = t[2]; rbh[np*2+1][1] = t[3];
                ldmx4(t, bBase + A_oVTl + np * 16 * ATROW + ks * 32);
                rbl[np*2][0] = t[0]; rbl[np*2][1] = t[1];
                rbl[np*2+1][0] = t[2]; rbl[np*2+1][1] = t[3];
            }
#pragma unroll
            for (int mt = 0; mt < 2; ++mt)
#pragma unroll
                for (int nt = 0; nt < 8; ++nt) mma16816(acc[mt][nt], rah[mt], rbh[nt]);
#pragma unroll
            for (int mt = 0; mt < 2; ++mt)
#pragma unroll
                for (int nt = 0; nt < 8; ++nt) mma16816(acc[mt][nt], rah[mt], rbl[nt]);
#pragma unroll
            for (int mt = 0; mt < 2; ++mt)
#pragma unroll
                for (int nt = 0; nt < 8; ++nt) mma16816(acc[mt][nt], ral[mt], rbh[nt]);
        }
        float* outp = KVb + ((size_t)bh * NCHUNK + c) * (DKK * DVV);
#pragma unroll
        for (int mt = 0; mt < 2; ++mt)
#pragma unroll
            for (int nt = 0; nt < 8; ++nt) {
                int kd = wm + mt * 16 + cr;
                int vd = wn + nt * 8 + cc;
                *reinterpret_cast<float2*>(&outp[(size_t)kd * 128 + vd]) =
                    make_float2(acc[mt][nt][0], acc[mt][nt][1]);
                *reinterpret_cast<float2*>(&outp[(size_t)(kd + 8) * 128 + vd]) =
                    make_float2(acc[mt][nt][2], acc[mt][nt][3]);
            }
    }
    __syncthreads();

    // ---- (b) O_intra = S_masked · v ----
    {
        int wm = (wid & 3) * 16, wn = (wid >> 2) * 64;
        float acc[8][4];
#pragma unroll
        for (int j = 0; j < 8; ++j)
#pragma unroll
            for (int r = 0; r < 4; ++r) acc[j][r] = 0.f;

        uint32_t aBase = sb + (wm + (lane & 15)) * ATROW + (lane >> 4) * 16;
        uint32_t bBase = sb + (wn + ((bg >> 1) * 8) + (lane & 7)) * ATROW + (bg & 1) * 16;
#pragma unroll
        for (int ks = 0; ks < 4; ++ks) {
            uint32_t rah[4], ral[4];
            ldmx4(rah, aBase + A_oSh + ks * 32);
            ldmx4(ral, aBase + A_oSl + ks * 32);
            uint32_t rbh[8][2], rbl[8][2];
#pragma unroll
            for (int np = 0; np < 4; ++np) {
                uint32_t t[4];
                ldmx4(t, bBase + A_oVTh + np * 16 * ATROW + ks * 32);
                rbh[np*2][0] = t[0]; rbh[np*2][1] = t[1];
                rbh[np*2+1][0] = t[2]; rbh[np*2+1][1] = t[3];
                ldmx4(t, bBase + A_oVTl + np * 16 * ATROW + ks * 32);
                rbl[np*2][0] = t[0]; rbl[np*2][1] = t[1];
                rbl[np*2+1][0] = t[2]; rbl[np*2+1][1] = t[3];
            }
#pragma unroll
            for (int nt = 0; nt < 8; ++nt) mma16816(acc[nt], rah, rbh[nt]);
#pragma unroll
            for (int nt = 0; nt < 8; ++nt) mma16816(acc[nt], rah, rbl[nt]);
#pragma unroll
            for (int nt = 0; nt < 8; ++nt) mma16816(acc[nt], ral, rbh[nt]);
        }
#pragma unroll
        for (int nt = 0; nt < 8; ++nt) {
            int i0 = wm + cr;
            int vd = wn + nt * 8 + cc;
            size_t g0 = ((size_t)((b * TLEN + t0 + i0) * NHEAD) + h) * DVV + vd;
            size_t g1 = ((size_t)((b * TLEN + t0 + i0 + 8) * NHEAD) + h) * DVV + vd;
            *reinterpret_cast<float2*>(&O[g0]) = make_float2(acc[nt][0], acc[nt][1]);
            *reinterpret_cast<float2*>(&O[g1]) = make_float2(acc[nt][2], acc[nt][3]);
        }
    }
}

// ---------------- exclusive prefix scan of KV over chunks -------------------
__global__ void scan_kernel(float* __restrict__ KVb)
{
    int e  = blockIdx.x * 256 + threadIdx.x;
    int bh = blockIdx.y;
    float* base = KVb + (size_t)bh * NCHUNK * DKK * DVV + e;
    float run = 0.f;
#pragma unroll 4
    for (int c = 0; c < NCHUNK; ++c) {
        float v = base[(size_t)c * DKK * DVV];
        base[(size_t)c * DKK * DVV] = run;
        run += v;
    }
}

// ---------------- phase C: O_final = O_intra + q@S, written as bf16 hi/lo ----
#define I_oQh 0
#define I_oQl 17408
#define I_oSTh 34816
#define I_oSTl 69632
#define ATTN_INTER_SMEM 104448

__global__ __launch_bounds__(256, 1)
void attn_inter_hmma(const float* __restrict__ Q,
                     const float* __restrict__ KVb,
                     const float* __restrict__ O,
                     __nv_bfloat16* __restrict__ OH,
                     __nv_bfloat16* __restrict__ OL)
{
    extern __shared__ char sm[];
    uint32_t sb = smem_to_u32(sm);
    int c = blockIdx.x, bh = blockIdx.y;
    int b = bh >> 3, h = bh & 7;
    int t0 = c * CHUNKSZ;
    int tid = threadIdx.x, wid = tid >> 5, lane = tid & 31;

#pragma unroll
    for (int it = 0; it < 8; ++it) {
        int idx = tid + it * 256;
        int m = idx & 63, d4 = idx >> 6;
        size_t g = ((size_t)((b * TLEN + t0 + m) * NHEAD) + h) * DKK + d4 * 4;
        float4 vq = *reinterpret_cast<const float4*>(Q + g);
        vq.x *= SCALE; vq.y *= SCALE; vq.z *= SCALE; vq.w *= SCALE;
        __nv_bfloat16 hh[4], ll[4];
        bsplit4a(vq, hh, ll);
        *reinterpret_cast<uint32_t*>(sm + I_oQh + m * AQROW + d4 * 8)     = pack2(hh[0], hh[1]);
        *reinterpret_cast<uint32_t*>(sm + I_oQh + m * AQROW + d4 * 8 + 4) = pack2(hh[2], hh[3]);
        *reinterpret_cast<uint32_t*>(sm + I_oQl + m * AQROW + d4 * 8)     = pack2(ll[0], ll[1]);
        *reinterpret_cast<uint32_t*>(sm + I_oQl + m * AQROW + d4 * 8 + 4) = pack2(ll[2], ll[3]);
    }
    const float* Sg = KVb + ((size_t)bh * NCHUNK + c) * (DKK * DVV);
#pragma unroll
    for (int it = 0; it < 16; ++it) {
        int idx = tid + it * 256;
        int kd = idx >> 5, v4 = idx & 31;
        float4 v = *reinterpret_cast<const float4*>(Sg + (size_t)kd * 128 + v4 * 4);
        __nv_bfloat16 hh[4], ll[4];
        bsplit4a(v, hh, ll);
#pragma unroll
        for (int j = 0; j < 4; ++j) {
            int vd = v4 * 4 + j;
            *reinterpret_cast<__nv_bfloat16*>(sm + I_oSTh + vd * AQROW + kd * 2) = hh[j];
            *reinterpret_cast<__nv_bfloat16*>(sm + I_oSTl + vd * AQROW + kd * 2) = ll[j];
        }
    }
    __syncthreads();

    int bg = lane >> 3;
    int wm = (wid & 3) * 16, wn = (wid >> 2) * 64;
    float acc[8][4];
#pragma unroll
    for (int j = 0; j < 8; ++j)
#pragma unroll
        for (int r = 0; r < 4; ++r) acc[j][r] = 0.f;

    uint32_t aBase = sb + (wm + (lane & 15)) * AQROW + (lane >> 4) * 16;
    uint32_t bBase = sb + (wn + ((bg >> 1) * 8) + (lane & 7)) * AQROW + (bg & 1) * 16;
#pragma unroll
    for (int ks = 0; ks < 8; ++ks) {
        uint32_t rah[4], ral[4];
        ldmx4(rah, aBase + I_oQh + ks * 32);
        ldmx4(ral, aBase + I_oQl + ks * 32);
        uint32_t rbh[8][2], rbl[8][2];
#pragma unroll
        for (int np = 0; np < 4; ++np) {
            uint32_t t[4];
            ldmx4(t, bBase + I_oSTh + np * 16 * AQROW + ks * 32);
            rbh[np*2][0] = t[0]; rbh[np*2][1] = t[1];
            rbh[np*2+1][0] = t[2]; rbh[np*2+1][1] = t[3];
            ldmx4(t, bBase + I_oSTl + np * 16 * AQROW + ks * 32);
            rbl[np*2][0] = t[0]; rbl[np*2][1] = t[1];
            rbl[np*2+1][0] = t[2]; rbl[np*2+1][1] = t[3];
        }
#pragma unroll
        for (int nt = 0; nt < 8; ++nt) mma16816(acc[nt], rah, rbh[nt]);
#pragma unroll
        for (int nt = 0; nt < 8; ++nt) mma16816(acc[nt], rah, rbl[nt]);
#pragma unroll
        for (int nt = 0; nt < 8; ++nt) mma16816(acc[nt], ral, rbh[nt]);
    }

    int cr = lane >> 2, cc = (lane & 3) * 2;
#pragma unroll
    for (int nt = 0; nt < 8; ++nt) {
        int i0 = wm + cr;
        int vd = wn + nt * 8 + cc;
        size_t g0 = ((size_t)((b * TLEN + t0 + i0) * NHEAD) + h) * DVV + vd;
        size_t g1 = ((size_t)((b * TLEN + t0 + i0 + 8) * NHEAD) + h) * DVV + vd;
        float2 o0 = *reinterpret_cast<const float2*>(&O[g0]);
        float2 o1 = *reinterpret_cast<const float2*>(&O[g1]);
        o0.x += acc[nt][0]; o0.y += acc[nt][1];
        o1.x += acc[nt][2]; o1.y += acc[nt][3];
        __nv_bfloat16 h0 = __float2bfloat16(o0.x), h1 = __float2bfloat16(o0.y);
        __nv_bfloat16 l0 = __float2bfloat16(o0.x - __bfloat162float(h0));
        __nv_bfloat16 l1 = __float2bfloat16(o0.y - __bfloat162float(h1));
        *reinterpret_cast<uint32_t*>(OH + g0) = pack2(h0, h1);
        *reinterpret_cast<uint32_t*>(OL + g0) = pack2(l0, l1);
        h0 = __float2bfloat16(o1.x); h1 = __float2bfloat16(o1.y);
        l0 = __float2bfloat16(o1.x - __bfloat162float(h0));
        l1 = __float2bfloat16(o1.y - __bfloat162float(h1));
        *reinterpret_cast<uint32_t*>(OH + g1) = pack2(h0, h1);
        *reinterpret_cast<uint32_t*>(OL + g1) = pack2(l0, l1);
    }
}

// ---------------- launch ----------------------------------------------------
extern "C" void kernel_launch(void* const* d_in, const int* in_sizes, int n_in,
                              void* d_out, int out_size)
{
    const float* x   = (const float*)d_in[0];
    const float* wq  = (const float*)d_in[1];
    const float* wk  = (const float*)d_in[2];
    const float* wv  = (const float*)d_in[3];
    const float* wo  = (const float*)d_in[4];
    const float* cq  = (const float*)d_in[5];
    const float* ck  = (const float*)d_in[6];
    const float* cv  = (const float*)d_in[7];
    const float* q1  = (const float*)d_in[8];
    const float* qb1 = (const float*)d_in[9];
    const float* q2  = (const float*)d_in[10];
    const float* qb2 = (const float*)d_in[11];
    const float* k1  = (const float*)d_in[12];
    const float* kb1 = (const float*)d_in[13];
    const float* k2  = (const float*)d_in[14];
    const float* kb2 = (const float*)d_in[15];
    float* out = (float*)d_out;

    float *qb, *kb, *vb, *qc, *kc, *vc, *qf, *kf, *ob, *kv;
    __nv_bfloat16 *xh, *xl, *wh, *wl, *oh, *ol, *fwh, *fwl;
    cudaGetSymbolAddress((void**)&qb, g_qb);
    cudaGetSymbolAddress((void**)&kb, g_kb);
    cudaGetSymbolAddress((void**)&vb, g_vb);
    cudaGetSymbolAddress((void**)&qc, g_qc);
    cudaGetSymbolAddress((void**)&kc, g_kc);
    cudaGetSymbolAddress((void**)&vc, g_vc);
    cudaGetSymbolAddress((void**)&qf, g_qf);
    cudaGetSymbolAddress((void**)&kf, g_kf);
    cudaGetSymbolAddress((void**)&ob, g_o);
    cudaGetSymbolAddress((void**)&kv, g_kv);
    cudaGetSymbolAddress((void**)&xh, g_xh);
    cudaGetSymbolAddress((void**)&xl, g_xl);
    cudaGetSymbolAddress((void**)&wh, g_wh);
    cudaGetSymbolAddress((void**)&wl, g_wl);
    cudaGetSymbolAddress((void**)&oh, g_oh);
    cudaGetSymbolAddress((void**)&ol, g_ol);
    cudaGetSymbolAddress((void**)&fwh, g_fwh);
    cudaGetSymbolAddress((void**)&fwl, g_fwl);

    // conv q/k outputs reuse g_qc/g_kc storage as bf16 hi/lo pairs
    __nv_bfloat16* qch = (__nv_bfloat16*)qc;
    __nv_bfloat16* qcl = qch + (size_t)MROWS * HID;
    __nv_bfloat16* kch = (__nv_bfloat16*)kc;
    __nv_bfloat16* kcl = kch + (size_t)MROWS * HID;

    static int attrs_set = 0;
    if (!attrs_set) {
        cudaFuncSetAttribute(hmma_gemm_qkv, cudaFuncAttributeMaxDynamicSharedMemorySize, GEMM_SMEM);
        cudaFuncSetAttribute(hmma_gemm_wo,  cudaFuncAttributeMaxDynamicSharedMemorySize, GEMM_SMEM);
        cudaFuncSetAttribute(fm_hmma3_kernel, cudaFuncAttributeMaxDynamicSharedMemorySize, FM_SMEM);
        cudaFuncSetAttribute(attn_intra_hmma, cudaFuncAttributeMaxDynamicSharedMemorySize, ATTN_INTRA_SMEM);
        cudaFuncSetAttribute(attn_inter_hmma, cudaFuncAttributeMaxDynamicSharedMemorySize, ATTN_INTER_SMEM);
        attrs_set = 1;
    }

    // conversions (bf16 hi/lo — proven)
    split_kernel<<<MROWS * HID / 4 / 256, 256>>>(x, xh, xl, MROWS * HID / 4);
    split_w_kernel<<<dim3(HH / 4 / 256, 4), 256>>>(wq, wk, wv, wo, wh, wl);
    split_fmw_kernel<<<dim3(16, 4), 256>>>(q1, q2, k1, k2, fwh, fwl);

    // q/k/v projections (merged, 512 threads, 3-pass, 5-buffer paired pipeline)
    hmma_gemm_qkv<<<dim3(HID / 128, MROWS / 128, 3), 512, GEMM_SMEM>>>(xh, xl, wh, wl, qb, kb, vb);

    // conv + silu (merged; q/k emit bf16 hi/lo)
    int nconv4 = MROWS * HID / 4 / 256;
    conv_silu4_kernel<<<dim3(nconv4, 3), 256>>>(qb, cq, qch, qcl,
                                                kb, ck, kch, kcl,
                                                vb, cv, vc);

    // feature maps (merged q/k, fully presplit inputs)
    fm_hmma3_kernel<<<dim3(FMROWS / 128, 2), 256, FM_SMEM>>>(
        qch, qcl, kch, kcl, fwh, fwl, qb1, qb2, kb1, kb2, qf, kf);

    // attention (bf16 3-pass)
    attn_intra_hmma<<<dim3(NCHUNK, BATCH * NHEAD), 256, ATTN_INTRA_SMEM>>>(qf, kf, vc, ob, kv);
    scan_kernel<<<dim3(DKK * DVV / 256, BATCH * NHEAD), 256>>>(kv);
    attn_inter_hmma<<<dim3(NCHUNK, BATCH * NHEAD), 256, ATTN_INTER_SMEM>>>(qf, kv, ob, oh, ol);

    // output projection (3-pass, 5-buffer paired pipeline)
    hmma_gemm_wo<<<dim3(HID / 128, MROWS / 128), 512, GEMM_SMEM>>>(oh, ol, wh + 3 * (size_t)HH, wl + 3 * (size_t)HH, out);
}

// round 15
// speedup vs baseline: 1.1127x; 1.1127x over previous
#include <cuda_runtime.h>
#include <cuda_bf16.h>
#include <math.h>
#include <cstdint>

#define HID 1024
#define BATCH 2
#define TLEN 4096
#define NHEAD 8
#define DKK 128
#define DVV 128
#define NCHUNK 64
#define CHUNKSZ 64
#define MROWS (BATCH*TLEN)          /* 8192 */
#define FMROWS (BATCH*TLEN*NHEAD)   /* 65536 */
#define HH (HID*HID)

#define SCALE 0.08838834764831845f  /* 128^-0.5 */

// ---------------- scratch ----------------------------------------------------
__device__ float g_qb[MROWS*HID];
__device__ float g_kb[MROWS*HID];
__device__ float g_vb[MROWS*HID];
__device__ float g_qc[MROWS*HID];   /* reused as bf16 hi/lo pair for q conv out */
__device__ float g_kc[MROWS*HID];   /* reused as bf16 hi/lo pair for k conv out */
__device__ float g_vc[MROWS*HID];
__device__ float g_qf[MROWS*HID];
__device__ float g_kf[MROWS*HID];
__device__ float g_o [MROWS*HID];
__device__ float g_kv[(size_t)BATCH*NHEAD*NCHUNK*DKK*DVV];
__device__ __nv_bfloat16 g_xh[MROWS*HID];
__device__ __nv_bfloat16 g_xl[MROWS*HID];
__device__ __nv_bfloat16 g_wh[4*HH];
__device__ __nv_bfloat16 g_wl[4*HH];
__device__ __nv_bfloat16 g_oh[MROWS*HID];
__device__ __nv_bfloat16 g_ol[MROWS*HID];
__device__ __nv_bfloat16 g_fwh[4*DKK*DKK];
__device__ __nv_bfloat16 g_fwl[4*DKK*DKK];

// ---------------- PTX helpers ------------------------------------------------
__device__ __forceinline__ uint32_t smem_to_u32(const void* p) {
    uint32_t a;
    asm("{ .reg .u64 t; cvta.to.shared.u64 t, %1; cvt.u32.u64 %0, t; }" : "=r"(a) : "l"(p));
    return a;
}
__device__ __forceinline__ void cp_async16(uint32_t dst, const void* src) {
    asm volatile("cp.async.cg.shared.global [%0], [%1], 16;" :: "r"(dst), "l"(src));
}
#define CP_COMMIT() asm volatile("cp.async.commit_group;" ::: "memory")
#define CP_WAIT1()  asm volatile("cp.async.wait_group 1;" ::: "memory")

__device__ __forceinline__ void ldmx4(uint32_t* r, uint32_t addr) {
    asm volatile("ldmatrix.sync.aligned.m8n8.x4.shared.b16 {%0,%1,%2,%3}, [%4];"
        : "=r"(r[0]), "=r"(r[1]), "=r"(r[2]), "=r"(r[3]) : "r"(addr));
}
__device__ __forceinline__ void mma16816(float* d, const uint32_t* a, const uint32_t* b) {
    asm volatile(
        "mma.sync.aligned.m16n8k16.row.col.f32.bf16.bf16.f32 "
        "{%0,%1,%2,%3}, {%4,%5,%6,%7}, {%8,%9}, {%0,%1,%2,%3};"
        : "+f"(d[0]), "+f"(d[1]), "+f"(d[2]), "+f"(d[3])
        : "r"(a[0]), "r"(a[1]), "r"(a[2]), "r"(a[3]), "r"(b[0]), "r"(b[1]));
}

__device__ __forceinline__ void bsplit4a(float4 v, __nv_bfloat16* h, __nv_bfloat16* l) {
    h[0] = __float2bfloat16(v.x); l[0] = __float2bfloat16(v.x - __bfloat162float(h[0]));
    h[1] = __float2bfloat16(v.y); l[1] = __float2bfloat16(v.y - __bfloat162float(h[1]));
    h[2] = __float2bfloat16(v.z); l[2] = __float2bfloat16(v.z - __bfloat162float(h[2]));
    h[3] = __float2bfloat16(v.w); l[3] = __float2bfloat16(v.w - __bfloat162float(h[3]));
}
__device__ __forceinline__ uint32_t pack2(__nv_bfloat16 a, __nv_bfloat16 b) {
    return ((uint32_t)__bfloat16_as_ushort(b) << 16) | __bfloat16_as_ushort(a);
}
__device__ __forceinline__ void bsplit4(float4 v, uint2& hu, uint2& lu) {
    __nv_bfloat16 h[4], l[4];
    bsplit4a(v, h, l);
    hu.x = pack2(h[0], h[1]); hu.y = pack2(h[2], h[3]);
    lu.x = pack2(l[0], l[1]); lu.y = pack2(l[2], l[3]);
}

// ---------------- fp32 -> bf16 hi/lo converters -------------------------------
__global__ void split_kernel(const float* __restrict__ X,
                             __nv_bfloat16* __restrict__ H,
                             __nv_bfloat16* __restrict__ L, int n4)
{
    int i = blockIdx.x * blockDim.x + threadIdx.x;
    if (i >= n4) return;
    float4 v = reinterpret_cast<const float4*>(X)[i];
    uint2 hu, lu;
    bsplit4(v, hu, lu);
    reinterpret_cast<uint2*>(H)[i] = hu;
    reinterpret_cast<uint2*>(L)[i] = lu;
}

__global__ void split_w_kernel(const float* __restrict__ W0, const float* __restrict__ W1,
                               const float* __restrict__ W2, const float* __restrict__ W3,
                               __nv_bfloat16* __restrict__ H, __nv_bfloat16* __restrict__ L)
{
    int z = blockIdx.y;
    const float* W = z == 0 ? W0 : (z == 1 ? W1 : (z == 2 ? W2 : W3));
    int i = blockIdx.x * blockDim.x + threadIdx.x;
    float4 v = reinterpret_cast<const float4*>(W)[i];
    uint2 hu, lu;
    bsplit4(v, hu, lu);
    size_t o = (size_t)z * (HH / 4) + i;
    reinterpret_cast<uint2*>(H)[o] = hu;
    reinterpret_cast<uint2*>(L)[o] = lu;
}

__global__ void split_fmw_kernel(const float* __restrict__ Q1, const float* __restrict__ Q2,
                                 const float* __restrict__ K1, const float* __restrict__ K2,
                                 __nv_bfloat16* __restrict__ FH, __nv_bfloat16* __restrict__ FL)
{
    int z = blockIdx.y;
    const float* W = z == 0 ? Q1 : (z == 1 ? Q2 : (z == 2 ? K1 : K2));
    int i = blockIdx.x * blockDim.x + threadIdx.x;
    float4 v = reinterpret_cast<const float4*>(W)[i];
    uint2 hu, lu;
    bsplit4(v, hu, lu);
    reinterpret_cast<uint2*>(FH)[z * 4096 + i] = hu;
    reinterpret_cast<uint2*>(FL)[z * 4096 + i] = lu;
}

// ---------------- HMMA bf16 3-pass GEMM body (512 threads, 16 warps) ---------
// R13-proven: 4-buffer cp.async pipeline, one barrier/stage, 2-Frag ping-pong.
#define ROWB 80
#define ARRB (128*ROWB)        /* 10240 */
#define BUFB (4*ARRB)          /* Ah,Al,Bh,Bl = 40960 */
#define GEMM_SMEM (4*BUFB)     /* 163840 */

struct Frag {
    uint32_t rah[2][4], ral[2][4];
    uint32_t rbh[4][2], rbl[4][2];
};

__device__ __forceinline__ void load_frag(Frag& f, uint32_t bb, int ks,
                                          int a_row, int a_kc, int b_row, int b_kc)
{
#pragma unroll
    for (int mt = 0; mt < 2; ++mt) {
        uint32_t ad = bb + (a_row + mt * 16) * ROWB + (a_kc + ks * 16) * 2;
        ldmx4(f.rah[mt], ad);
        ldmx4(f.ral[mt], ad + ARRB);
    }
#pragma unroll
    for (int np = 0; np < 2; ++np) {
        uint32_t bd = bb + 2 * ARRB + (b_row + np * 16) * ROWB + (b_kc + ks * 16) * 2;
        uint32_t t[4];
        ldmx4(t, bd);
        f.rbh[np*2][0] = t[0]; f.rbh[np*2][1] = t[1];
        f.rbh[np*2+1][0] = t[2]; f.rbh[np*2+1][1] = t[3];
        ldmx4(t, bd + ARRB);
        f.rbl[np*2][0] = t[0]; f.rbl[np*2][1] = t[1];
        f.rbl[np*2+1][0] = t[2]; f.rbl[np*2+1][1] = t[3];
    }
}

__device__ __forceinline__ void mma_frag(float acc[2][4][4], const Frag& f)
{
#pragma unroll
    for (int mt = 0; mt < 2; ++mt)
#pragma unroll
        for (int nt = 0; nt < 4; ++nt)
            mma16816(acc[mt][nt], f.rah[mt], f.rbh[nt]);
#pragma unroll
    for (int mt = 0; mt < 2; ++mt)
#pragma unroll
        for (int nt = 0; nt < 4; ++nt)
            mma16816(acc[mt][nt], f.rah[mt], f.rbl[nt]);
#pragma unroll
    for (int mt = 0; mt < 2; ++mt)
#pragma unroll
        for (int nt = 0; nt < 4; ++nt)
            mma16816(acc[mt][nt], f.ral[mt], f.rbh[nt]);
}

__device__ __forceinline__ void gemm3_body(
    const __nv_bfloat16* __restrict__ Ah, const __nv_bfloat16* __restrict__ Al,
    const __nv_bfloat16* __restrict__ Bh, const __nv_bfloat16* __restrict__ Bl,
    float* __restrict__ C, int N, int K, char* smem)
{
    uint32_t sb = smem_to_u32(smem);
    int tid = threadIdx.x, wid = tid >> 5, lane = tid & 31;
    int m0 = blockIdx.y * 128, n0 = blockIdx.x * 128;
    int warp_m = (wid & 3) * 32, warp_n = (wid >> 2) * 32;
    const int NST = K / 32;

    float acc[2][4][4];
#pragma unroll
    for (int i = 0; i < 2; ++i)
#pragma unroll
        for (int j = 0; j < 4; ++j)
#pragma unroll
            for (int r = 0; r < 4; ++r) acc[i][j][r] = 0.f;

#define PREFETCH(s) do { \
        int _k0 = (s) * 32; \
        uint32_t _bb = sb + ((s) & 3) * BUFB; \
        int _row = tid >> 2, _ch = tid & 3; \
        uint32_t _off = _row * ROWB + _ch * 16; \
        size_t _ga = (size_t)(m0 + _row) * K + _k0 + _ch * 8; \
        size_t _gb = (size_t)(n0 + _row) * K + _k0 + _ch * 8; \
        cp_async16(_bb + _off,          Ah + _ga); \
        cp_async16(_bb + ARRB + _off,   Al + _ga); \
        cp_async16(_bb + 2*ARRB + _off, Bh + _gb); \
        cp_async16(_bb + 3*ARRB + _off, Bl + _gb); \
    } while (0)

    PREFETCH(0); CP_COMMIT();
    PREFETCH(1); CP_COMMIT();

    int a_row = warp_m + (lane & 15);
    int a_kc  = (lane >> 4) * 8;
    int bg    = lane >> 3;
    int b_row = warp_n + ((bg >> 1) * 8) + (lane & 7);
    int b_kc  = (bg & 1) * 8;

    Frag f0, f1;
    bool carried = false;

    for (int s = 0; s < NST; ++s) {
        if (s + 2 < NST) PREFETCH(s + 2);
        CP_COMMIT();
        CP_WAIT1();          // stages <= s+1 complete (own thread)
        __syncthreads();     // all threads' waits done -> stages s, s+1 visible

        uint32_t bb = sb + (s & 3) * BUFB;
        if (!carried) load_frag(f0, bb, 0, a_row, a_kc, b_row, b_kc);
        load_frag(f1, bb, 1, a_row, a_kc, b_row, b_kc);
        mma_frag(acc, f0);
        if (s + 1 < NST) {
            load_frag(f0, sb + ((s + 1) & 3) * BUFB, 0, a_row, a_kc, b_row, b_kc);
            carried = true;
        }
        mma_frag(acc, f1);
    }
#undef PREFETCH

    int cr = lane >> 2, cc = (lane & 3) * 2;
#pragma unroll
    for (int mt = 0; mt < 2; ++mt)
#pragma unroll
        for (int nt = 0; nt < 4; ++nt) {
            int row = m0 + warp_m + mt * 16 + cr;
            int col = n0 + warp_n + nt * 8 + cc;
            *reinterpret_cast<float2*>(&C[(size_t)row * N + col]) =
                make_float2(acc[mt][nt][0], acc[mt][nt][1]);
            *reinterpret_cast<float2*>(&C[(size_t)(row + 8) * N + col]) =
                make_float2(acc[mt][nt][2], acc[mt][nt][3]);
        }
}

__global__ __launch_bounds__(512, 1)
void hmma_gemm_qkv(const __nv_bfloat16* __restrict__ Xh, const __nv_bfloat16* __restrict__ Xl,
                   const __nv_bfloat16* __restrict__ Wh, const __nv_bfloat16* __restrict__ Wl,
                   float* __restrict__ Cq, float* __restrict__ Ck, float* __restrict__ Cv)
{
    extern __shared__ char smem[];
    int z = blockIdx.z;
    const __nv_bfloat16* Bh = Wh + (size_t)z * HH;
    const __nv_bfloat16* Bl = Wl + (size_t)z * HH;
    float* C = z == 0 ? Cq : (z == 1 ? Ck : Cv);
    gemm3_body(Xh, Xl, Bh, Bl, C, HID, HID, smem);
}

__global__ __launch_bounds__(512, 1)
void hmma_gemm_wo(const __nv_bfloat16* __restrict__ Ah, const __nv_bfloat16* __restrict__ Al,
                  const __nv_bfloat16* __restrict__ Bh, const __nv_bfloat16* __restrict__ Bl,
                  float* __restrict__ C)
{
    extern __shared__ char smem[];
    gemm3_body(Ah, Al, Bh, Bl, C, HID, HID, smem);
}

// ---------------- causal depthwise conv1d (K=4) + SiLU, merged, 4 t/thread ---
// q/k outputs emit bf16 hi/lo (fm input); v stays fp32 (attention input).
__global__ void conv_silu4_kernel(const float* __restrict__ X0, const float* __restrict__ W0,
                                  __nv_bfloat16* __restrict__ Y0h, __nv_bfloat16* __restrict__ Y0l,
                                  const float* __restrict__ X1, const float* __restrict__ W1,
                                  __nv_bfloat16* __restrict__ Y1h, __nv_bfloat16* __restrict__ Y1l,
                                  const float* __restrict__ X2, const float* __restrict__ W2,
                                  float* __restrict__ Y2)
{
    int z = blockIdx.y;
    const float* X = z == 0 ? X0 : (z == 1 ? X1 : X2);
    const float* W = z == 0 ? W0 : (z == 1 ? W1 : W2);

    int idx = blockIdx.x * blockDim.x + threadIdx.x;
    int d = idx & (HID - 1);
    int tq = idx >> 10;
    int t0 = (tq & (TLEN / 4 - 1)) * 4;
    size_t row0 = (size_t)tq * 4;
    const float* xp = X + row0 * HID + d;
    float4 wv = *reinterpret_cast<const float4*>(&W[d * 4]);
    float xv[7];
#pragma unroll
    for (int o = 0; o < 7; ++o) {
        int t = t0 + o - 3;
        xv[o] = (t >= 0) ? xp[(ptrdiff_t)(o - 3) * HID] : 0.f;
    }
    if (z == 2) {
#pragma unroll
        for (int j = 0; j < 4; ++j) {
            float s = wv.x * xv[j] + wv.y * xv[j + 1] + wv.z * xv[j + 2] + wv.w * xv[j + 3];
            Y2[(row0 + j) * HID + d] = s / (1.f + expf(-s));
        }
    } else {
        __nv_bfloat16* YH = z == 0 ? Y0h : Y1h;
        __nv_bfloat16* YL = z == 0 ? Y0l : Y1l;
#pragma unroll
        for (int j = 0; j < 4; ++j) {
            float s = wv.x * xv[j] + wv.y * xv[j + 1] + wv.z * xv[j + 2] + wv.w * xv[j + 3];
            float y = s / (1.f + expf(-s));
            __nv_bfloat16 h = __float2bfloat16(y);
            __nv_bfloat16 l = __float2bfloat16(y - __bfloat162float(h));
            YH[(row0 + j) * HID + d] = h;
            YL[(row0 + j) * HID + d] = l;
        }
    }
}

// ---------------- hadamard feature map via HMMA bf16 3-pass (merged q/k) -----
#define FROWB 272
#define FSZ (128*FROWB)          /* 34816 per array */
#define FM_SMEM (6*FSZ)          /* 208896 */

__global__ __launch_bounds__(256, 1)
void fm_hmma3_kernel(const __nv_bfloat16* __restrict__ AqH, const __nv_bfloat16* __restrict__ AqL,
                     const __nv_bfloat16* __restrict__ AkH, const __nv_bfloat16* __restrict__ AkL,
                     const __nv_bfloat16* __restrict__ FH, const __nv_bfloat16* __restrict__ FL,
                     const float* __restrict__ Bq1, const float* __restrict__ Bq2,
                     const float* __restrict__ Bk1, const float* __restrict__ Bk2,
                     float* __restrict__ Yq, float* __restrict__ Yk)
{
    extern __shared__ char smem[];
    int z = blockIdx.y;
    const __nv_bfloat16* AH = z ? AkH : AqH;
    const __nv_bfloat16* AL = z ? AkL : AqL;
    const float* B1 = z ? Bk1 : Bq1;
    const float* B2 = z ? Bk2 : Bq2;
    float* Y        = z ? Yk  : Yq;
    const __nv_bfloat16* W1h = FH + (size_t)(z * 2)     * 16384;
    const __nv_bfloat16* W1l = FL + (size_t)(z * 2)     * 16384;
    const __nv_bfloat16* W2h = FH + (size_t)(z * 2 + 1) * 16384;
    const __nv_bfloat16* W2l = FL + (size_t)(z * 2 + 1) * 16384;

    uint32_t sb = smem_to_u32(smem);
    uint32_t sAh = sb, sAl = sb + FSZ;
    uint32_t sW1h = sb + 2 * FSZ, sW1l = sb + 3 * FSZ;
    uint32_t sW2h = sb + 4 * FSZ, sW2l = sb + 5 * FSZ;
    int tid = threadIdx.x, wid = tid >> 5, lane = tid & 31;
    int m0 = blockIdx.x * 128;
    int warp_m = (wid & 3) * 32, warp_n = (wid >> 2) * 64;

    // stage A hi/lo via direct uint4 copies (presplit by conv)
#pragma unroll
    for (int it = 0; it < 8; ++it) {
        int idx = tid + it * 256;
        int m = idx >> 4, c16 = idx & 15;
        uint32_t off = m * FROWB + c16 * 16;
        size_t gsrc = (size_t)(m0 + m) * 16 + c16;
        *reinterpret_cast<uint4*>(smem + off)       = reinterpret_cast<const uint4*>(AH)[gsrc];
        *reinterpret_cast<uint4*>(smem + FSZ + off) = reinterpret_cast<const uint4*>(AL)[gsrc];
    }
#pragma unroll
    for (int it = 0; it < 8; ++it) {
        int idx = tid + it * 256;
        int e = idx >> 4, c16 = idx & 15;
        uint32_t off = e * FROWB + c16 * 16;
        *reinterpret_cast<uint4*>(smem + 2 * FSZ + off) = reinterpret_cast<const uint4*>(W1h)[idx];
        *reinterpret_cast<uint4*>(smem + 3 * FSZ + off) = reinterpret_cast<const uint4*>(W1l)[idx];
        *reinterpret_cast<uint4*>(smem + 4 * FSZ + off) = reinterpret_cast<const uint4*>(W2h)[idx];
        *reinterpret_cast<uint4*>(smem + 5 * FSZ + off) = reinterpret_cast<const uint4*>(W2l)[idx];
    }
    __syncthreads();

    int a_row = warp_m + (lane & 15);
    int a_kc  = (lane >> 4) * 8;
    int bg    = lane >> 3;
    int b_row = ((bg >> 1) * 8) + (lane & 7);
    int b_kc  = (bg & 1) * 8;
    int cr = lane >> 2, cc = (lane & 3) * 2;

#pragma unroll
    for (int nh = 0; nh < 2; ++nh) {
        float acc1[2][4][4], acc2[2][4][4];
#pragma unroll
        for (int i = 0; i < 2; ++i)
#pragma unroll
            for (int j = 0; j < 4; ++j)
#pragma unroll
                for (int r = 0; r < 4; ++r) { acc1[i][j][r] = 0.f; acc2[i][j][r] = 0.f; }

#pragma unroll
        for (int ks = 0; ks < 8; ++ks) {
            uint32_t rah[2][4], ral[2][4];
#pragma unroll
            for (int mt = 0; mt < 2; ++mt) {
                uint32_t ad = (a_row + mt * 16) * FROWB + (a_kc + ks * 16) * 2;
                ldmx4(rah[mt], sAh + ad);
                ldmx4(ral[mt], sAl + ad);
            }
            uint32_t rb1h[4][2], rb1l[4][2], rb2h[4][2], rb2l[4][2];
#pragma unroll
            for (int np = 0; np < 2; ++np) {
                uint32_t roff = (warp_n + nh * 32 + np * 16 + b_row) * FROWB + (b_kc + ks * 16) * 2;
                uint32_t t[4];
                ldmx4(t, sW1h + roff);
                rb1h[np*2][0] = t[0]; rb1h[np*2][1] = t[1];
                rb1h[np*2+1][0] = t[2]; rb1h[np*2+1][1] = t[3];
                ldmx4(t, sW1l + roff);
                rb1l[np*2][0] = t[0]; rb1l[np*2][1] = t[1];
                rb1l[np*2+1][0] = t[2]; rb1l[np*2+1][1] = t[3];
                ldmx4(t, sW2h + roff);
                rb2h[np*2][0] = t[0]; rb2h[np*2][1] = t[1];
                rb2h[np*2+1][0] = t[2]; rb2h[np*2+1][1] = t[3];
                ldmx4(t, sW2l + roff);
                rb2l[np*2][0] = t[0]; rb2l[np*2][1] = t[1];
                rb2l[np*2+1][0] = t[2]; rb2l[np*2+1][1] = t[3];
            }
#pragma unroll
            for (int mt = 0; mt < 2; ++mt)
#pragma unroll
                for (int nt = 0; nt < 4; ++nt) mma16816(acc1[mt][nt], rah[mt], rb1h[nt]);
#pragma unroll
            for (int mt = 0; mt < 2; ++mt)
#pragma unroll
                for (int nt = 0; nt < 4; ++nt) mma16816(acc2[mt][nt], rah[mt], rb2h[nt]);
#pragma unroll
            for (int mt = 0; mt < 2; ++mt)
#pragma unroll
                for (int nt = 0; nt < 4; ++nt) mma16816(acc1[mt][nt], ral[mt], rb1h[nt]);
#pragma unroll
            for (int mt = 0; mt < 2; ++mt)
#pragma unroll
                for (int nt = 0; nt < 4; ++nt) mma16816(acc2[mt][nt], ral[mt], rb2h[nt]);
#pragma unroll
            for (int mt = 0; mt < 2; ++mt)
#pragma unroll
                for (int nt = 0; nt < 4; ++nt) mma16816(acc1[mt][nt], rah[mt], rb1l[nt]);
#pragma unroll
            for (int mt = 0; mt < 2; ++mt)
#pragma unroll
                for (int nt = 0; nt < 4; ++nt) mma16816(acc2[mt][nt], rah[mt], rb2l[nt]);
        }

#pragma unroll
        for (int mt = 0; mt < 2; ++mt)
#pragma unroll
            for (int nt = 0; nt < 4; ++nt) {
                int col = warp_n + nh * 32 + nt * 8 + cc;
                float b1v0 = B1[col], b1v1 = B1[col + 1];
                float b2v0 = B2[col], b2v1 = B2[col + 1];
                int row0 = m0 + warp_m + mt * 16 + cr;
                float y0 = (acc1[mt][nt][0] + b1v0) * (acc2[mt][nt][0] + b2v0);
                float y1 = (acc1[mt][nt][1] + b1v1) * (acc2[mt][nt][1] + b2v1);
                float y2 = (acc1[mt][nt][2] + b1v0) * (acc2[mt][nt][2] + b2v0);
                float y3 = (acc1[mt][nt][3] + b1v1) * (acc2[mt][nt][3] + b2v1);
                *reinterpret_cast<float2*>(&Y[(size_t)row0 * 128 + col])       = make_float2(y0, y1);
                *reinterpret_cast<float2*>(&Y[(size_t)(row0 + 8) * 128 + col]) = make_float2(y2, y3);
            }
    }
}

// ---------------- phase A: intra-chunk attention + KV via HMMA bf16 3-pass ---
#define AQROW 272
#define ATROW 144
#define A_oQh 0
#define A_oQl 17408
#define A_oKh 34816
#define A_oKl 52224
#define A_oKTh 69632
#define A_oKTl 88064
#define A_oVTh 106496
#define A_oVTl 124928
#define A_oSh  143360
#define A_oSl  152576
#define ATTN_INTRA_SMEM 161792

__global__ __launch_bounds__(256, 1)
void attn_intra_hmma(const float* __restrict__ Q,
                     const float* __restrict__ Kf,
                     const float* __restrict__ V,
                     float* __restrict__ O,
                     float* __restrict__ KVb)
{
    extern __shared__ char sm[];
    uint32_t sb = smem_to_u32(sm);
    int c = blockIdx.x, bh = blockIdx.y;
    int b = bh >> 3, h = bh & 7;
    int t0 = c * CHUNKSZ;
    int tid = threadIdx.x, wid = tid >> 5, lane = tid & 31;

#pragma unroll
    for (int it = 0; it < 8; ++it) {
        int idx = tid + it * 256;
        int m = idx & 63, d4 = idx >> 6;
        size_t g = ((size_t)((b * TLEN + t0 + m) * NHEAD) + h) * DKK + d4 * 4;
        __nv_bfloat16 hh[4], ll[4];

        float4 vq = *reinterpret_cast<const float4*>(Q + g);
        vq.x *= SCALE; vq.y *= SCALE; vq.z *= SCALE; vq.w *= SCALE;
        bsplit4a(vq, hh, ll);
        *reinterpret_cast<uint32_t*>(sm + A_oQh + m * AQROW + d4 * 8)     = pack2(hh[0], hh[1]);
        *reinterpret_cast<uint32_t*>(sm + A_oQh + m * AQROW + d4 * 8 + 4) = pack2(hh[2], hh[3]);
        *reinterpret_cast<uint32_t*>(sm + A_oQl + m * AQROW + d4 * 8)     = pack2(ll[0], ll[1]);
        *reinterpret_cast<uint32_t*>(sm + A_oQl + m * AQROW + d4 * 8 + 4) = pack2(ll[2], ll[3]);

        float4 vk = *reinterpret_cast<const float4*>(Kf + g);
        bsplit4a(vk, hh, ll);
        *reinterpret_cast<uint32_t*>(sm + A_oKh + m * AQROW + d4 * 8)     = pack2(hh[0], hh[1]);
        *reinterpret_cast<uint32_t*>(sm + A_oKh + m * AQROW + d4 * 8 + 4) = pack2(hh[2], hh[3]);
        *reinterpret_cast<uint32_t*>(sm + A_oKl + m * AQROW + d4 * 8)     = pack2(ll[0], ll[1]);
        *reinterpret_cast<uint32_t*>(sm + A_oKl + m * AQROW + d4 * 8 + 4) = pack2(ll[2], ll[3]);
#pragma unroll
        for (int j = 0; j < 4; ++j) {
            int d = d4 * 4 + j;
            *reinterpret_cast<__nv_bfloat16*>(sm + A_oKTh + d * ATROW + m * 2) = hh[j];
            *reinterpret_cast<__nv_bfloat16*>(sm + A_oKTl + d * ATROW + m * 2) = ll[j];
        }

        float4 vv = *reinterpret_cast<const float4*>(V + g);
        bsplit4a(vv, hh, ll);
#pragma unroll
        for (int j = 0; j < 4; ++j) {
            int d = d4 * 4 + j;
            *reinterpret_cast<__nv_bfloat16*>(sm + A_oVTh + d * ATROW + m * 2) = hh[j];
            *reinterpret_cast<__nv_bfloat16*>(sm + A_oVTl + d * ATROW + m * 2) = ll[j];
        }
    }
    __syncthreads();

    int bg = lane >> 3;
    int cr = lane >> 2, cc = (lane & 3) * 2;

    // ---- (a) S = (q*scale) k^T, masked, stored hi/lo ----
    {
        int wm = (wid & 3) * 16, wn = (wid >> 2) * 32;
        float accS[4][4];
#pragma unroll
        for (int j = 0; j < 4; ++j)
#pragma unroll
            for (int r = 0; r < 4; ++r) accS[j][r] = 0.f;

        uint32_t aAddr = sb + (wm + (lane & 15)) * AQROW + (lane >> 4) * 16;
        uint32_t bAddr = sb + (wn + ((bg >> 1) * 8) + (lane & 7)) * AQROW + (bg & 1) * 16;
#pragma unroll
        for (int ks = 0; ks < 8; ++ks) {
            uint32_t rah[4], ral[4];
            ldmx4(rah, aAddr + A_oQh + ks * 32);
            ldmx4(ral, aAddr + A_oQl + ks * 32);
            uint32_t rbh[4][2], rbl[4][2];
#pragma unroll
            for (int np = 0; np < 2; ++np) {
                uint32_t t[4];
                ldmx4(t, bAddr + A_oKh + np * 16 * AQROW + ks * 32);
                rbh[np*2][0] = t[0]; rbh[np*2][1] = t[1];
                rbh[np*2+1][0] = t[2]; rbh[np*2+1][1] = t[3];
                ldmx4(t, bAddr + A_oKl + np * 16 * AQROW + ks * 32);
                rbl[np*2][0] = t[0]; rbl[np*2][1] = t[1];
                rbl[np*2+1][0] = t[2]; rbl[np*2+1][1] = t[3];
            }
#pragma unroll
            for (int nt = 0; nt < 4; ++nt) mma16816(accS[nt], rah, rbh[nt]);
#pragma unroll
            for (int nt = 0; nt < 4; ++nt) mma16816(accS[nt], rah, rbl[nt]);
#pragma unroll
            for (int nt = 0; nt < 4; ++nt) mma16816(accS[nt], ral, rbh[nt]);
        }
        int r0 = wm + cr;
#pragma unroll
        for (int nt = 0; nt < 4; ++nt) {
            int c0 = wn + nt * 8 + cc;
            float v00 = (c0     <= r0    ) ? accS[nt][0] : 0.f;
            float v01 = (c0 + 1 <= r0    ) ? accS[nt][1] : 0.f;
            float v10 = (c0     <= r0 + 8) ? accS[nt][2] : 0.f;
            float v11 = (c0 + 1 <= r0 + 8) ? accS[nt][3] : 0.f;
            __nv_bfloat16 h00 = __float2bfloat16(v00), h01 = __float2bfloat16(v01);
            __nv_bfloat16 h10 = __float2bfloat16(v10), h11 = __float2bfloat16(v11);
            __nv_bfloat16 l00 = __float2bfloat16(v00 - __bfloat162float(h00));
            __nv_bfloat16 l01 = __float2bfloat16(v01 - __bfloat162float(h01));
            __nv_bfloat16 l10 = __float2bfloat16(v10 - __bfloat162float(h10));
            __nv_bfloat16 l11 = __float2bfloat16(v11 - __bfloat162float(h11));
            *reinterpret_cast<uint32_t*>(sm + A_oSh + r0 * ATROW + c0 * 2)       = pack2(h00, h01);
            *reinterpret_cast<uint32_t*>(sm + A_oSl + r0 * ATROW + c0 * 2)       = pack2(l00, l01);
            *reinterpret_cast<uint32_t*>(sm + A_oSh + (r0 + 8) * ATROW + c0 * 2) = pack2(h10, h11);
            *reinterpret_cast<uint32_t*>(sm + A_oSl + (r0 + 8) * ATROW + c0 * 2) = pack2(l10, l11);
        }
    }

    // ---- (c) KV = k^T v ----
    {
        int wm = (wid & 3) * 32, wn = (wid >> 2) * 64;
        float acc[2][8][4];
#pragma unroll
        for (int i = 0; i < 2; ++i)
#pragma unroll
            for (int j = 0; j < 8; ++j)
#pragma unroll
                for (int r = 0; r < 4; ++r) acc[i][j][r] = 0.f;

        uint32_t aBase = sb + (wm + (lane & 15)) * ATROW + (lane >> 4) * 16;
        uint32_t bBase = sb + (wn + ((bg >> 1) * 8) + (lane & 7)) * ATROW + (bg & 1) * 16;
#pragma unroll
        for (int ks = 0; ks < 4; ++ks) {
            uint32_t rah[2][4], ral[2][4];
#pragma unroll
            for (int mt = 0; mt < 2; ++mt) {
                ldmx4(rah[mt], aBase + A_oKTh + mt * 16 * ATROW + ks * 32);
                ldmx4(ral[mt], aBase + A_oKTl + mt * 16 * ATROW + ks * 32);
            }
            uint32_t rbh[8][2], rbl[8][2];
#pragma unroll
            for (int np = 0; np < 4; ++np) {
                uint32_t t[4];
                ldmx4(t, bBase + A_oVTh + np * 16 * ATROW + ks * 32);
                rbh[np*2][0] = t[0]; rbh[np*2][1] = t[1];
                rbh[np*2+1][0] = t[2]; rbh[np*2+1][1] = t[3];
                ldmx4(t, bBase + A_oVTl + np * 16 * ATROW + ks * 32);
                rbl[np*2][0] = t[0]; rbl[np*2][1] = t[1];
                rbl[np*2+1][0] = t[2]; rbl[np*2+1][1] = t[3];
            }
#pragma unroll
            for (int mt = 0; mt < 2; ++mt)
#pragma unroll
                for (int nt = 0; nt < 8; ++nt) mma16816(acc[mt][nt], rah[mt], rbh[nt]);
#pragma unroll
            for (int mt = 0; mt < 2; ++mt)
#pragma unroll
                for (int nt = 0; nt < 8; ++nt) mma16816(acc[mt][nt], rah[mt], rbl[nt]);
#pragma unroll
            for (int mt = 0; mt < 2; ++mt)
#pragma unroll
                for (int nt = 0; nt < 8; ++nt) mma16816(acc[mt][nt], ral[mt], rbh[nt]);
        }
        float* outp = KVb + ((size_t)bh * NCHUNK + c) * (DKK * DVV);
#pragma unroll
        for (int mt = 0; mt < 2; ++mt)
#pragma unroll
            for (int nt = 0; nt < 8; ++nt) {
                int kd = wm + mt * 16 + cr;
                int vd = wn + nt * 8 + cc;
                *reinterpret_cast<float2*>(&outp[(size_t)kd * 128 + vd]) =
                    make_float2(acc[mt][nt][0], acc[mt][nt][1]);
                *reinterpret_cast<float2*>(&outp[(size_t)(kd + 8) * 128 + vd]) =
                    make_float2(acc[mt][nt][2], acc[mt][nt][3]);
            }
    }
    __syncthreads();

    // ---- (b) O_intra = S_masked · v ----
    {
        int wm = (wid & 3) * 16, wn = (wid >> 2) * 64;
        float acc[8][4];
#pragma unroll
        for (int j = 0; j < 8; ++j)
#pragma unroll
            for (int r = 0; r < 4; ++r) acc[j][r] = 0.f;

        uint32_t aBase = sb + (wm + (lane & 15)) * ATROW + (lane >> 4) * 16;
        uint32_t bBase = sb + (wn + ((bg >> 1) * 8) + (lane & 7)) * ATROW + (bg & 1) * 16;
#pragma unroll
        for (int ks = 0; ks < 4; ++ks) {
            uint32_t rah[4], ral[4];
            ldmx4(rah, aBase + A_oSh + ks * 32);
            ldmx4(ral, aBase + A_oSl + ks * 32);
            uint32_t rbh[8][2], rbl[8][2];
#pragma unroll
            for (int np = 0; np < 4; ++np) {
                uint32_t t[4];
                ldmx4(t, bBase + A_oVTh + np * 16 * ATROW + ks * 32);
                rbh[np*2][0] = t[0]; rbh[np*2][1] = t[1];
                rbh[np*2+1][0] = t[2]; rbh[np*2+1][1] = t[3];
                ldmx4(t, bBase + A_oVTl + np * 16 * ATROW + ks * 32);
                rbl[np*2][0] = t[0]; rbl[np*2][1] = t[1];
                rbl[np*2+1][0] = t[2]; rbl[np*2+1][1] = t[3];
            }
#pragma unroll
            for (int nt = 0; nt < 8; ++nt) mma16816(acc[nt], rah, rbh[nt]);
#pragma unroll
            for (int nt = 0; nt < 8; ++nt) mma16816(acc[nt], rah, rbl[nt]);
#pragma unroll
            for (int nt = 0; nt < 8; ++nt) mma16816(acc[nt], ral, rbh[nt]);
        }
#pragma unroll
        for (int nt = 0; nt < 8; ++nt) {
            int i0 = wm + cr;
            int vd = wn + nt * 8 + cc;
            size_t g0 = ((size_t)((b * TLEN + t0 + i0) * NHEAD) + h) * DVV + vd;
            size_t g1 = ((size_t)((b * TLEN + t0 + i0 + 8) * NHEAD) + h) * DVV + vd;
            *reinterpret_cast<float2*>(&O[g0]) = make_float2(acc[nt][0], acc[nt][1]);
            *reinterpret_cast<float2*>(&O[g1]) = make_float2(acc[nt][2], acc[nt][3]);
        }
    }
}

// ---------------- exclusive prefix scan of KV over chunks -------------------
__global__ void scan_kernel(float* __restrict__ KVb)
{
    int e  = blockIdx.x * 256 + threadIdx.x;
    int bh = blockIdx.y;
    float* base = KVb + (size_t)bh * NCHUNK * DKK * DVV + e;
    float run = 0.f;
#pragma unroll 4
    for (int c = 0; c < NCHUNK; ++c) {
        float v = base[(size_t)c * DKK * DVV];
        base[(size_t)c * DKK * DVV] = run;
        run += v;
    }
}

// ---------------- phase C: O_final = O_intra + q@S, written as bf16 hi/lo ----
#define I_oQh 0
#define I_oQl 17408
#define I_oSTh 34816
#define I_oSTl 69632
#define ATTN_INTER_SMEM 104448

__global__ __launch_bounds__(256, 1)
void attn_inter_hmma(const float* __restrict__ Q,
                     const float* __restrict__ KVb,
                     const float* __restrict__ O,
                     __nv_bfloat16* __restrict__ OH,
                     __nv_bfloat16* __restrict__ OL)
{
    extern __shared__ char sm[];
    uint32_t sb = smem_to_u32(sm);
    int c = blockIdx.x, bh = blockIdx.y;
    int b = bh >> 3, h = bh & 7;
    int t0 = c * CHUNKSZ;
    int tid = threadIdx.x, wid = tid >> 5, lane = tid & 31;

#pragma unroll
    for (int it = 0; it < 8; ++it) {
        int idx = tid + it * 256;
        int m = idx & 63, d4 = idx >> 6;
        size_t g = ((size_t)((b * TLEN + t0 + m) * NHEAD) + h) * DKK + d4 * 4;
        float4 vq = *reinterpret_cast<const float4*>(Q + g);
        vq.x *= SCALE; vq.y *= SCALE; vq.z *= SCALE; vq.w *= SCALE;
        __nv_bfloat16 hh[4], ll[4];
        bsplit4a(vq, hh, ll);
        *reinterpret_cast<uint32_t*>(sm + I_oQh + m * AQROW + d4 * 8)     = pack2(hh[0], hh[1]);
        *reinterpret_cast<uint32_t*>(sm + I_oQh + m * AQROW + d4 * 8 + 4) = pack2(hh[2], hh[3]);
        *reinterpret_cast<uint32_t*>(sm + I_oQl + m * AQROW + d4 * 8)     = pack2(ll[0], ll[1]);
        *reinterpret_cast<uint32_t*>(sm + I_oQl + m * AQROW + d4 * 8 + 4) = pack2(ll[2], ll[3]);
    }
    const float* Sg = KVb + ((size_t)bh * NCHUNK + c) * (DKK * DVV);
#pragma unroll
    for (int it = 0; it < 16; ++it) {
        int idx = tid + it * 256;
        int kd = idx >> 5, v4 = idx & 31;
        float4 v = *reinterpret_cast<const float4*>(Sg + (size_t)kd * 128 + v4 * 4);
        __nv_bfloat16 hh[4], ll[4];
        bsplit4a(v, hh, ll);
#pragma unroll
        for (int j = 0; j < 4; ++j) {
            int vd = v4 * 4 + j;
            *reinterpret_cast<__nv_bfloat16*>(sm + I_oSTh + vd * AQROW + kd * 2) = hh[j];
            *reinterpret_cast<__nv_bfloat16*>(sm + I_oSTl + vd * AQROW + kd * 2) = ll[j];
        }
    }
    __syncthreads();

    int bg = lane >> 3;
    int wm = (wid & 3) * 16, wn = (wid >> 2) * 64;
    float acc[8][4];
#pragma unroll
    for (int j = 0; j < 8; ++j)
#pragma unroll
        for (int r = 0; r < 4; ++r) acc[j][r] = 0.f;

    uint32_t aBase = sb + (wm + (lane & 15)) * AQROW + (lane >> 4) * 16;
    uint32_t bBase = sb + (wn + ((bg >> 1) * 8) + (lane & 7)) * AQROW + (bg & 1) * 16;
#pragma unroll
    for (int ks = 0; ks < 8; ++ks) {
        uint32_t rah[4], ral[4];
        ldmx4(rah, aBase + I_oQh + ks * 32);
        ldmx4(ral, aBase + I_oQl + ks * 32);
        uint32_t rbh[8][2], rbl[8][2];
#pragma unroll
        for (int np = 0; np < 4; ++np) {
            uint32_t t[4];
            ldmx4(t, bBase + I_oSTh + np * 16 * AQROW + ks * 32);
            rbh[np*2][0] = t[0]; rbh[np*2][1] = t[1];
            rbh[np*2+1][0] = t[2]; rbh[np*2+1][1] = t[3];
            ldmx4(t, bBase + I_oSTl + np * 16 * AQROW + ks * 32);
            rbl[np*2][0] = t[0]; rbl[np*2][1] = t[1];
            rbl[np*2+1][0] = t[2]; rbl[np*2+1][1] = t[3];
        }
#pragma unroll
        for (int nt = 0; nt < 8; ++nt) mma16816(acc[nt], rah, rbh[nt]);
#pragma unroll
        for (int nt = 0; nt < 8; ++nt) mma16816(acc[nt], rah, rbl[nt]);
#pragma unroll
        for (int nt = 0; nt < 8; ++nt) mma16816(acc[nt], ral, rbh[nt]);
    }

    int cr = lane >> 2, cc = (lane & 3) * 2;
#pragma unroll
    for (int nt = 0; nt < 8; ++nt) {
        int i0 = wm + cr;
        int vd = wn + nt * 8 + cc;
        size_t g0 = ((size_t)((b * TLEN + t0 + i0) * NHEAD) + h) * DVV + vd;
        size_t g1 = ((size_t)((b * TLEN + t0 + i0 + 8) * NHEAD) + h) * DVV + vd;
        float2 o0 = *reinterpret_cast<const float2*>(&O[g0]);
        float2 o1 = *reinterpret_cast<const float2*>(&O[g1]);
        o0.x += acc[nt][0]; o0.y += acc[nt][1];
        o1.x += acc[nt][2]; o1.y += acc[nt][3];
        __nv_bfloat16 h0 = __float2bfloat16(o0.x), h1 = __float2bfloat16(o0.y);
        __nv_bfloat16 l0 = __float2bfloat16(o0.x - __bfloat162float(h0));
        __nv_bfloat16 l1 = __float2bfloat16(o0.y - __bfloat162float(h1));
        *reinterpret_cast<uint32_t*>(OH + g0) = pack2(h0, h1);
        *reinterpret_cast<uint32_t*>(OL + g0) = pack2(l0, l1);
        h0 = __float2bfloat16(o1.x); h1 = __float2bfloat16(o1.y);
        l0 = __float2bfloat16(o1.x - __bfloat162float(h0));
        l1 = __float2bfloat16(o1.y - __bfloat162float(h1));
        *reinterpret_cast<uint32_t*>(OH + g1) = pack2(h0, h1);
        *reinterpret_cast<uint32_t*>(OL + g1) = pack2(l0, l1);
    }
}

// ---------------- launch ----------------------------------------------------
extern "C" void kernel_launch(void* const* d_in, const int* in_sizes, int n_in,
                              void* d_out, int out_size)
{
    const float* x   = (const float*)d_in[0];
    const float* wq  = (const float*)d_in[1];
    const float* wk  = (const float*)d_in[2];
    const float* wv  = (const float*)d_in[3];
    const float* wo  = (const float*)d_in[4];
    const float* cq  = (const float*)d_in[5];
    const float* ck  = (const float*)d_in[6];
    const float* cv  = (const float*)d_in[7];
    const float* q1  = (const float*)d_in[8];
    const float* qb1 = (const float*)d_in[9];
    const float* q2  = (const float*)d_in[10];
    const float* qb2 = (const float*)d_in[11];
    const float* k1  = (const float*)d_in[12];
    const float* kb1 = (const float*)d_in[13];
    const float* k2  = (const float*)d_in[14];
    const float* kb2 = (const float*)d_in[15];
    float* out = (float*)d_out;

    float *qb, *kb, *vb, *qc, *kc, *vc, *qf, *kf, *ob, *kv;
    __nv_bfloat16 *xh, *xl, *wh, *wl, *oh, *ol, *fwh, *fwl;
    cudaGetSymbolAddress((void**)&qb, g_qb);
    cudaGetSymbolAddress((void**)&kb, g_kb);
    cudaGetSymbolAddress((void**)&vb, g_vb);
    cudaGetSymbolAddress((void**)&qc, g_qc);
    cudaGetSymbolAddress((void**)&kc, g_kc);
    cudaGetSymbolAddress((void**)&vc, g_vc);
    cudaGetSymbolAddress((void**)&qf, g_qf);
    cudaGetSymbolAddress((void**)&kf, g_kf);
    cudaGetSymbolAddress((void**)&ob, g_o);
    cudaGetSymbolAddress((void**)&kv, g_kv);
    cudaGetSymbolAddress((void**)&xh, g_xh);
    cudaGetSymbolAddress((void**)&xl, g_xl);
    cudaGetSymbolAddress((void**)&wh, g_wh);
    cudaGetSymbolAddress((void**)&wl, g_wl);
    cudaGetSymbolAddress((void**)&oh, g_oh);
    cudaGetSymbolAddress((void**)&ol, g_ol);
    cudaGetSymbolAddress((void**)&fwh, g_fwh);
    cudaGetSymbolAddress((void**)&fwl, g_fwl);

    __nv_bfloat16* qch = (__nv_bfloat16*)qc;
    __nv_bfloat16* qcl = qch + (size_t)MROWS * HID;
    __nv_bfloat16* kch = (__nv_bfloat16*)kc;
    __nv_bfloat16* kcl = kch + (size_t)MROWS * HID;

    static int attrs_set = 0;
    if (!attrs_set) {
        cudaFuncSetAttribute(hmma_gemm_qkv, cudaFuncAttributeMaxDynamicSharedMemorySize, GEMM_SMEM);
        cudaFuncSetAttribute(hmma_gemm_wo,  cudaFuncAttributeMaxDynamicSharedMemorySize, GEMM_SMEM);
        cudaFuncSetAttribute(fm_hmma3_kernel, cudaFuncAttributeMaxDynamicSharedMemorySize, FM_SMEM);
        cudaFuncSetAttribute(attn_intra_hmma, cudaFuncAttributeMaxDynamicSharedMemorySize, ATTN_INTRA_SMEM);
        cudaFuncSetAttribute(attn_inter_hmma, cudaFuncAttributeMaxDynamicSharedMemorySize, ATTN_INTER_SMEM);
        attrs_set = 1;
    }

    // conversions (bf16 hi/lo — proven)
    split_kernel<<<MROWS * HID / 4 / 256, 256>>>(x, xh, xl, MROWS * HID / 4);
    split_w_kernel<<<dim3(HH / 4 / 256, 4), 256>>>(wq, wk, wv, wo, wh, wl);
    split_fmw_kernel<<<dim3(16, 4), 256>>>(q1, q2, k1, k2, fwh, fwl);

    // q/k/v projections (R13 pipeline: 4-buffer, 1 barrier, 2-Frag ping-pong)
    hmma_gemm_qkv<<<dim3(HID / 128, MROWS / 128, 3), 512, GEMM_SMEM>>>(xh, xl, wh, wl, qb, kb, vb);

    // conv + silu (merged; q/k emit bf16 hi/lo)
    int nconv4 = MROWS * HID / 4 / 256;
    conv_silu4_kernel<<<dim3(nconv4, 3), 256>>>(qb, cq, qch, qcl,
                                                kb, ck, kch, kcl,
                                                vb, cv, vc);

    // feature maps (merged q/k, fully presplit inputs)
    fm_hmma3_kernel<<<dim3(FMROWS / 128, 2), 256, FM_SMEM>>>(
        qch, qcl, kch, kcl, fwh, fwl, qb1, qb2, kb1, kb2, qf, kf);

    // attention (bf16 3-pass)
    attn_intra_hmma<<<dim3(NCHUNK, BATCH * NHEAD), 256, ATTN_INTRA_SMEM>>>(qf, kf, vc, ob, kv);
    scan_kernel<<<dim3(DKK * DVV / 256, BATCH * NHEAD), 256>>>(kv);
    attn_inter_hmma<<<dim3(NCHUNK, BATCH * NHEAD), 256, ATTN_INTER_SMEM>>>(qf, kv, ob, oh, ol);

    // output projection (R13 pipeline)
    hmma_gemm_wo<<<dim3(HID / 128, MROWS / 128), 512, GEMM_SMEM>>>(oh, ol, wh + 3 * (size_t)HH, wl + 3 * (size_t)HH, out);
}

// round 16
// speedup vs baseline: 1.1333x; 1.0186x over previous
#include <cuda_runtime.h>
#include <cuda_bf16.h>
#include <math.h>
#include <cstdint>

#define HID 1024
#define BATCH 2
#define TLEN 4096
#define NHEAD 8
#define DKK 128
#define DVV 128
#define NCHUNK 64
#define CHUNKSZ 64
#define MROWS (BATCH*TLEN)          /* 8192 */
#define FMROWS (BATCH*TLEN*NHEAD)   /* 65536 */
#define HH (HID*HID)

#define SCALE 0.08838834764831845f  /* 128^-0.5 */

// ---------------- scratch ----------------------------------------------------
__device__ float g_qb[MROWS*HID];
__device__ float g_kb[MROWS*HID];
__device__ float g_vb[MROWS*HID];
__device__ float g_qc[MROWS*HID];
__device__ float g_kc[MROWS*HID];
__device__ float g_vc[MROWS*HID];
__device__ float g_qf[MROWS*HID];   /* reused: bf16 qfh + qfl (scaled, presplit) */
__device__ float g_kf[MROWS*HID];
__device__ float g_o [MROWS*HID];
__device__ float g_kv[(size_t)BATCH*NHEAD*NCHUNK*DKK*DVV];
__device__ __nv_bfloat16 g_xh[MROWS*HID];
__device__ __nv_bfloat16 g_xl[MROWS*HID];
__device__ __nv_bfloat16 g_wh[4*HH];
__device__ __nv_bfloat16 g_wl[4*HH];
__device__ __nv_bfloat16 g_oh[MROWS*HID];
__device__ __nv_bfloat16 g_ol[MROWS*HID];
__device__ __nv_bfloat16 g_fwh[4*DKK*DKK];
__device__ __nv_bfloat16 g_fwl[4*DKK*DKK];

// ---------------- PTX helpers ------------------------------------------------
__device__ __forceinline__ uint32_t smem_to_u32(const void* p) {
    uint32_t a;
    asm("{ .reg .u64 t; cvta.to.shared.u64 t, %1; cvt.u32.u64 %0, t; }" : "=r"(a) : "l"(p));
    return a;
}
__device__ __forceinline__ void cp_async16(uint32_t dst, const void* src) {
    asm volatile("cp.async.cg.shared.global [%0], [%1], 16;" :: "r"(dst), "l"(src));
}
#define CP_COMMIT() asm volatile("cp.async.commit_group;" ::: "memory")
#define CP_WAIT1()  asm volatile("cp.async.wait_group 1;" ::: "memory")

__device__ __forceinline__ void ldmx4(uint32_t* r, uint32_t addr) {
    asm volatile("ldmatrix.sync.aligned.m8n8.x4.shared.b16 {%0,%1,%2,%3}, [%4];"
        : "=r"(r[0]), "=r"(r[1]), "=r"(r[2]), "=r"(r[3]) : "r"(addr));
}
__device__ __forceinline__ void mma16816(float* d, const uint32_t* a, const uint32_t* b) {
    asm volatile(
        "mma.sync.aligned.m16n8k16.row.col.f32.bf16.bf16.f32 "
        "{%0,%1,%2,%3}, {%4,%5,%6,%7}, {%8,%9}, {%0,%1,%2,%3};"
        : "+f"(d[0]), "+f"(d[1]), "+f"(d[2]), "+f"(d[3])
        : "r"(a[0]), "r"(a[1]), "r"(a[2]), "r"(a[3]), "r"(b[0]), "r"(b[1]));
}

__device__ __forceinline__ void bsplit4a(float4 v, __nv_bfloat16* h, __nv_bfloat16* l) {
    h[0] = __float2bfloat16(v.x); l[0] = __float2bfloat16(v.x - __bfloat162float(h[0]));
    h[1] = __float2bfloat16(v.y); l[1] = __float2bfloat16(v.y - __bfloat162float(h[1]));
    h[2] = __float2bfloat16(v.z); l[2] = __float2bfloat16(v.z - __bfloat162float(h[2]));
    h[3] = __float2bfloat16(v.w); l[3] = __float2bfloat16(v.w - __bfloat162float(h[3]));
}
__device__ __forceinline__ uint32_t pack2(__nv_bfloat16 a, __nv_bfloat16 b) {
    return ((uint32_t)__bfloat16_as_ushort(b) << 16) | __bfloat16_as_ushort(a);
}
__device__ __forceinline__ void bsplit4(float4 v, uint2& hu, uint2& lu) {
    __nv_bfloat16 h[4], l[4];
    bsplit4a(v, h, l);
    hu.x = pack2(h[0], h[1]); hu.y = pack2(h[2], h[3]);
    lu.x = pack2(l[0], l[1]); lu.y = pack2(l[2], l[3]);
}
__device__ __forceinline__ void bsplit1(float v, __nv_bfloat16& h, __nv_bfloat16& l) {
    h = __float2bfloat16(v);
    l = __float2bfloat16(v - __bfloat162float(h));
}

// ---------------- fp32 -> bf16 hi/lo converters -------------------------------
__global__ void split_kernel(const float* __restrict__ X,
                             __nv_bfloat16* __restrict__ H,
                             __nv_bfloat16* __restrict__ L, int n4)
{
    int i = blockIdx.x * blockDim.x + threadIdx.x;
    if (i >= n4) return;
    float4 v = reinterpret_cast<const float4*>(X)[i];
    uint2 hu, lu;
    bsplit4(v, hu, lu);
    reinterpret_cast<uint2*>(H)[i] = hu;
    reinterpret_cast<uint2*>(L)[i] = lu;
}

__global__ void split_w_kernel(const float* __restrict__ W0, const float* __restrict__ W1,
                               const float* __restrict__ W2, const float* __restrict__ W3,
                               __nv_bfloat16* __restrict__ H, __nv_bfloat16* __restrict__ L)
{
    int z = blockIdx.y;
    const float* W = z == 0 ? W0 : (z == 1 ? W1 : (z == 2 ? W2 : W3));
    int i = blockIdx.x * blockDim.x + threadIdx.x;
    float4 v = reinterpret_cast<const float4*>(W)[i];
    uint2 hu, lu;
    bsplit4(v, hu, lu);
    size_t o = (size_t)z * (HH / 4) + i;
    reinterpret_cast<uint2*>(H)[o] = hu;
    reinterpret_cast<uint2*>(L)[o] = lu;
}

__global__ void split_fmw_kernel(const float* __restrict__ Q1, const float* __restrict__ Q2,
                                 const float* __restrict__ K1, const float* __restrict__ K2,
                                 __nv_bfloat16* __restrict__ FH, __nv_bfloat16* __restrict__ FL)
{
    int z = blockIdx.y;
    const float* W = z == 0 ? Q1 : (z == 1 ? Q2 : (z == 2 ? K1 : K2));
    int i = blockIdx.x * blockDim.x + threadIdx.x;
    float4 v = reinterpret_cast<const float4*>(W)[i];
    uint2 hu, lu;
    bsplit4(v, hu, lu);
    reinterpret_cast<uint2*>(FH)[z * 4096 + i] = hu;
    reinterpret_cast<uint2*>(FL)[z * 4096 + i] = lu;
}

// ---------------- HMMA bf16 3-pass GEMM body (512 threads, 16 warps) ---------
// R13-proven: 4-buffer cp.async pipeline, one barrier/stage, 2-Frag ping-pong.
#define ROWB 80
#define ARRB (128*ROWB)        /* 10240 */
#define BUFB (4*ARRB)          /* Ah,Al,Bh,Bl = 40960 */
#define GEMM_SMEM (4*BUFB)     /* 163840 */

struct Frag {
    uint32_t rah[2][4], ral[2][4];
    uint32_t rbh[4][2], rbl[4][2];
};

__device__ __forceinline__ void load_frag(Frag& f, uint32_t bb, int ks,
                                          int a_row, int a_kc, int b_row, int b_kc)
{
#pragma unroll
    for (int mt = 0; mt < 2; ++mt) {
        uint32_t ad = bb + (a_row + mt * 16) * ROWB + (a_kc + ks * 16) * 2;
        ldmx4(f.rah[mt], ad);
        ldmx4(f.ral[mt], ad + ARRB);
    }
#pragma unroll
    for (int np = 0; np < 2; ++np) {
        uint32_t bd = bb + 2 * ARRB + (b_row + np * 16) * ROWB + (b_kc + ks * 16) * 2;
        uint32_t t[4];
        ldmx4(t, bd);
        f.rbh[np*2][0] = t[0]; f.rbh[np*2][1] = t[1];
        f.rbh[np*2+1][0] = t[2]; f.rbh[np*2+1][1] = t[3];
        ldmx4(t, bd + ARRB);
        f.rbl[np*2][0] = t[0]; f.rbl[np*2][1] = t[1];
        f.rbl[np*2+1][0] = t[2]; f.rbl[np*2+1][1] = t[3];
    }
}

__device__ __forceinline__ void mma_frag(float acc[2][4][4], const Frag& f)
{
#pragma unroll
    for (int mt = 0; mt < 2; ++mt)
#pragma unroll
        for (int nt = 0; nt < 4; ++nt)
            mma16816(acc[mt][nt], f.rah[mt], f.rbh[nt]);
#pragma unroll
    for (int mt = 0; mt < 2; ++mt)
#pragma unroll
        for (int nt = 0; nt < 4; ++nt)
            mma16816(acc[mt][nt], f.rah[mt], f.rbl[nt]);
#pragma unroll
    for (int mt = 0; mt < 2; ++mt)
#pragma unroll
        for (int nt = 0; nt < 4; ++nt)
            mma16816(acc[mt][nt], f.ral[mt], f.rbh[nt]);
}

__device__ __forceinline__ void gemm3_body(
    const __nv_bfloat16* __restrict__ Ah, const __nv_bfloat16* __restrict__ Al,
    const __nv_bfloat16* __restrict__ Bh, const __nv_bfloat16* __restrict__ Bl,
    float* __restrict__ C, int N, int K, char* smem)
{
    uint32_t sb = smem_to_u32(smem);
    int tid = threadIdx.x, wid = tid >> 5, lane = tid & 31;
    int m0 = blockIdx.y * 128, n0 = blockIdx.x * 128;
    int warp_m = (wid & 3) * 32, warp_n = (wid >> 2) * 32;
    const int NST = K / 32;

    float acc[2][4][4];
#pragma unroll
    for (int i = 0; i < 2; ++i)
#pragma unroll
        for (int j = 0; j < 4; ++j)
#pragma unroll
            for (int r = 0; r < 4; ++r) acc[i][j][r] = 0.f;

#define PREFETCH(s) do { \
        int _k0 = (s) * 32; \
        uint32_t _bb = sb + ((s) & 3) * BUFB; \
        int _row = tid >> 2, _ch = tid & 3; \
        uint32_t _off = _row * ROWB + _ch * 16; \
        size_t _ga = (size_t)(m0 + _row) * K + _k0 + _ch * 8; \
        size_t _gb = (size_t)(n0 + _row) * K + _k0 + _ch * 8; \
        cp_async16(_bb + _off,          Ah + _ga); \
        cp_async16(_bb + ARRB + _off,   Al + _ga); \
        cp_async16(_bb + 2*ARRB + _off, Bh + _gb); \
        cp_async16(_bb + 3*ARRB + _off, Bl + _gb); \
    } while (0)

    PREFETCH(0); CP_COMMIT();
    PREFETCH(1); CP_COMMIT();

    int a_row = warp_m + (lane & 15);
    int a_kc  = (lane >> 4) * 8;
    int bg    = lane >> 3;
    int b_row = warp_n + ((bg >> 1) * 8) + (lane & 7);
    int b_kc  = (bg & 1) * 8;

    Frag f0, f1;
    bool carried = false;

    for (int s = 0; s < NST; ++s) {
        if (s + 2 < NST) PREFETCH(s + 2);
        CP_COMMIT();
        CP_WAIT1();
        __syncthreads();

        uint32_t bb = sb + (s & 3) * BUFB;
        if (!carried) load_frag(f0, bb, 0, a_row, a_kc, b_row, b_kc);
        load_frag(f1, bb, 1, a_row, a_kc, b_row, b_kc);
        mma_frag(acc, f0);
        if (s + 1 < NST) {
            load_frag(f0, sb + ((s + 1) & 3) * BUFB, 0, a_row, a_kc, b_row, b_kc);
            carried = true;
        }
        mma_frag(acc, f1);
    }
#undef PREFETCH

    int cr = lane >> 2, cc = (lane & 3) * 2;
#pragma unroll
    for (int mt = 0; mt < 2; ++mt)
#pragma unroll
        for (int nt = 0; nt < 4; ++nt) {
            int row = m0 + warp_m + mt * 16 + cr;
            int col = n0 + warp_n + nt * 8 + cc;
            *reinterpret_cast<float2*>(&C[(size_t)row * N + col]) =
                make_float2(acc[mt][nt][0], acc[mt][nt][1]);
            *reinterpret_cast<float2*>(&C[(size_t)(row + 8) * N + col]) =
                make_float2(acc[mt][nt][2], acc[mt][nt][3]);
        }
}

__global__ __launch_bounds__(512, 1)
void hmma_gemm_qkv(const __nv_bfloat16* __restrict__ Xh, const __nv_bfloat16* __restrict__ Xl,
                   const __nv_bfloat16* __restrict__ Wh, const __nv_bfloat16* __restrict__ Wl,
                   float* __restrict__ Cq, float* __restrict__ Ck, float* __restrict__ Cv)
{
    extern __shared__ char smem[];
    int z = blockIdx.z;
    const __nv_bfloat16* Bh = Wh + (size_t)z * HH;
    const __nv_bfloat16* Bl = Wl + (size_t)z * HH;
    float* C = z == 0 ? Cq : (z == 1 ? Ck : Cv);
    gemm3_body(Xh, Xl, Bh, Bl, C, HID, HID, smem);
}

__global__ __launch_bounds__(512, 1)
void hmma_gemm_wo(const __nv_bfloat16* __restrict__ Ah, const __nv_bfloat16* __restrict__ Al,
                  const __nv_bfloat16* __restrict__ Bh, const __nv_bfloat16* __restrict__ Bl,
                  float* __restrict__ C)
{
    extern __shared__ char smem[];
    gemm3_body(Ah, Al, Bh, Bl, C, HID, HID, smem);
}

// ---------------- causal depthwise conv1d (K=4) + SiLU, merged, 4 t/thread ---
__global__ void conv_silu4_kernel(const float* __restrict__ X0, const float* __restrict__ W0, float* __restrict__ Y0,
                                  const float* __restrict__ X1, const float* __restrict__ W1, float* __restrict__ Y1,
                                  const float* __restrict__ X2, const float* __restrict__ W2, float* __restrict__ Y2)
{
    int z = blockIdx.y;
    const float* X = z == 0 ? X0 : (z == 1 ? X1 : X2);
    const float* W = z == 0 ? W0 : (z == 1 ? W1 : W2);
    float* Y       = z == 0 ? Y0 : (z == 1 ? Y1 : Y2);

    int idx = blockIdx.x * blockDim.x + threadIdx.x;
    int d = idx & (HID - 1);
    int tq = idx >> 10;
    int t0 = (tq & (TLEN / 4 - 1)) * 4;
    size_t row0 = (size_t)tq * 4;
    const float* xp = X + row0 * HID + d;
    float4 wv = *reinterpret_cast<const float4*>(&W[d * 4]);
    float xv[7];
#pragma unroll
    for (int o = 0; o < 7; ++o) {
        int t = t0 + o - 3;
        xv[o] = (t >= 0) ? xp[(ptrdiff_t)(o - 3) * HID] : 0.f;
    }
#pragma unroll
    for (int j = 0; j < 4; ++j) {
        float s = wv.x * xv[j] + wv.y * xv[j + 1] + wv.z * xv[j + 2] + wv.w * xv[j + 3];
        Y[(row0 + j) * HID + d] = s / (1.f + expf(-s));
    }
}

// ---------------- hadamard feature map via HMMA bf16 3-pass (merged q/k) -----
// q output (z=0) written as SCALE-folded bf16 hi/lo; k output (z=1) fp32.
#define FROWB 272
#define FSZ (128*FROWB)          /* 34816 per array */
#define FM_SMEM (6*FSZ)          /* 208896 */

__global__ __launch_bounds__(256, 1)
void fm_hmma3_kernel(const float* __restrict__ Aq, const float* __restrict__ Ak,
                     const __nv_bfloat16* __restrict__ FH, const __nv_bfloat16* __restrict__ FL,
                     const float* __restrict__ Bq1, const float* __restrict__ Bq2,
                     const float* __restrict__ Bk1, const float* __restrict__ Bk2,
                     __nv_bfloat16* __restrict__ QFH, __nv_bfloat16* __restrict__ QFL,
                     float* __restrict__ Yk)
{
    extern __shared__ char smem[];
    int z = blockIdx.y;
    const float* A  = z ? Ak  : Aq;
    const float* B1 = z ? Bk1 : Bq1;
    const float* B2 = z ? Bk2 : Bq2;
    const __nv_bfloat16* W1h = FH + (size_t)(z * 2)     * 16384;
    const __nv_bfloat16* W1l = FL + (size_t)(z * 2)     * 16384;
    const __nv_bfloat16* W2h = FH + (size_t)(z * 2 + 1) * 16384;
    const __nv_bfloat16* W2l = FL + (size_t)(z * 2 + 1) * 16384;

    uint32_t sb = smem_to_u32(smem);
    uint32_t sAh = sb, sAl = sb + FSZ;
    uint32_t sW1h = sb + 2 * FSZ, sW1l = sb + 3 * FSZ;
    uint32_t sW2h = sb + 4 * FSZ, sW2l = sb + 5 * FSZ;
    int tid = threadIdx.x, wid = tid >> 5, lane = tid & 31;
    int m0 = blockIdx.x * 128;
    int warp_m = (wid & 3) * 32, warp_n = (wid >> 2) * 64;

    // stage A hi/lo (per-CTA split)
#pragma unroll
    for (int it = 0; it < 16; ++it) {
        int idx = tid + it * 256;
        int m = idx >> 5, d4 = idx & 31;
        float4 v = *reinterpret_cast<const float4*>(&A[(size_t)(m0 + m) * 128 + d4 * 4]);
        uint2 hu, lu; bsplit4(v, hu, lu);
        *reinterpret_cast<uint2*>(smem + (m * FROWB + d4 * 8))       = hu;
        *reinterpret_cast<uint2*>(smem + FSZ + (m * FROWB + d4 * 8)) = lu;
    }
    // stage presplit weights
#pragma unroll
    for (int it = 0; it < 8; ++it) {
        int idx = tid + it * 256;
        int e = idx >> 4, c16 = idx & 15;
        uint32_t off = e * FROWB + c16 * 16;
        *reinterpret_cast<uint4*>(smem + 2 * FSZ + off) = reinterpret_cast<const uint4*>(W1h)[idx];
        *reinterpret_cast<uint4*>(smem + 3 * FSZ + off) = reinterpret_cast<const uint4*>(W1l)[idx];
        *reinterpret_cast<uint4*>(smem + 4 * FSZ + off) = reinterpret_cast<const uint4*>(W2h)[idx];
        *reinterpret_cast<uint4*>(smem + 5 * FSZ + off) = reinterpret_cast<const uint4*>(W2l)[idx];
    }
    __syncthreads();

    int a_row = warp_m + (lane & 15);
    int a_kc  = (lane >> 4) * 8;
    int bg    = lane >> 3;
    int b_row = ((bg >> 1) * 8) + (lane & 7);
    int b_kc  = (bg & 1) * 8;
    int cr = lane >> 2, cc = (lane & 3) * 2;

#pragma unroll
    for (int nh = 0; nh < 2; ++nh) {
        float acc1[2][4][4], acc2[2][4][4];
#pragma unroll
        for (int i = 0; i < 2; ++i)
#pragma unroll
            for (int j = 0; j < 4; ++j)
#pragma unroll
                for (int r = 0; r < 4; ++r) { acc1[i][j][r] = 0.f; acc2[i][j][r] = 0.f; }

#pragma unroll
        for (int ks = 0; ks < 8; ++ks) {
            uint32_t rah[2][4], ral[2][4];
#pragma unroll
            for (int mt = 0; mt < 2; ++mt) {
                uint32_t ad = (a_row + mt * 16) * FROWB + (a_kc + ks * 16) * 2;
                ldmx4(rah[mt], sAh + ad);
                ldmx4(ral[mt], sAl + ad);
            }
            uint32_t rb1h[4][2], rb1l[4][2], rb2h[4][2], rb2l[4][2];
#pragma unroll
            for (int np = 0; np < 2; ++np) {
                uint32_t roff = (warp_n + nh * 32 + np * 16 + b_row) * FROWB + (b_kc + ks * 16) * 2;
                uint32_t t[4];
                ldmx4(t, sW1h + roff);
                rb1h[np*2][0] = t[0]; rb1h[np*2][1] = t[1];
                rb1h[np*2+1][0] = t[2]; rb1h[np*2+1][1] = t[3];
                ldmx4(t, sW1l + roff);
                rb1l[np*2][0] = t[0]; rb1l[np*2][1] = t[1];
                rb1l[np*2+1][0] = t[2]; rb1l[np*2+1][1] = t[3];
                ldmx4(t, sW2h + roff);
                rb2h[np*2][0] = t[0]; rb2h[np*2][1] = t[1];
                rb2h[np*2+1][0] = t[2]; rb2h[np*2+1][1] = t[3];
                ldmx4(t, sW2l + roff);
                rb2l[np*2][0] = t[0]; rb2l[np*2][1] = t[1];
                rb2l[np*2+1][0] = t[2]; rb2l[np*2+1][1] = t[3];
            }
#pragma unroll
            for (int mt = 0; mt < 2; ++mt)
#pragma unroll
                for (int nt = 0; nt < 4; ++nt) mma16816(acc1[mt][nt], rah[mt], rb1h[nt]);
#pragma unroll
            for (int mt = 0; mt < 2; ++mt)
#pragma unroll
                for (int nt = 0; nt < 4; ++nt) mma16816(acc2[mt][nt], rah[mt], rb2h[nt]);
#pragma unroll
            for (int mt = 0; mt < 2; ++mt)
#pragma unroll
                for (int nt = 0; nt < 4; ++nt) mma16816(acc1[mt][nt], ral[mt], rb1h[nt]);
#pragma unroll
            for (int mt = 0; mt < 2; ++mt)
#pragma unroll
                for (int nt = 0; nt < 4; ++nt) mma16816(acc2[mt][nt], ral[mt], rb2h[nt]);
#pragma unroll
            for (int mt = 0; mt < 2; ++mt)
#pragma unroll
                for (int nt = 0; nt < 4; ++nt) mma16816(acc1[mt][nt], rah[mt], rb1l[nt]);
#pragma unroll
            for (int mt = 0; mt < 2; ++mt)
#pragma unroll
                for (int nt = 0; nt < 4; ++nt) mma16816(acc2[mt][nt], rah[mt], rb2l[nt]);
        }

#pragma unroll
        for (int mt = 0; mt < 2; ++mt)
#pragma unroll
            for (int nt = 0; nt < 4; ++nt) {
                int col = warp_n + nh * 32 + nt * 8 + cc;
                float b1v0 = B1[col], b1v1 = B1[col + 1];
                float b2v0 = B2[col], b2v1 = B2[col + 1];
                int row0 = m0 + warp_m + mt * 16 + cr;
                float y0 = (acc1[mt][nt][0] + b1v0) * (acc2[mt][nt][0] + b2v0);
                float y1 = (acc1[mt][nt][1] + b1v1) * (acc2[mt][nt][1] + b2v1);
                float y2 = (acc1[mt][nt][2] + b1v0) * (acc2[mt][nt][2] + b2v0);
                float y3 = (acc1[mt][nt][3] + b1v1) * (acc2[mt][nt][3] + b2v1);
                if (z == 0) {
                    // q: fold SCALE, split to bf16 hi/lo (packed, coalesced)
                    __nv_bfloat16 h0, l0, h1, l1;
                    bsplit1(y0 * SCALE, h0, l0); bsplit1(y1 * SCALE, h1, l1);
                    *reinterpret_cast<uint32_t*>(QFH + (size_t)row0 * 128 + col) = pack2(h0, h1);
                    *reinterpret_cast<uint32_t*>(QFL + (size_t)row0 * 128 + col) = pack2(l0, l1);
                    bsplit1(y2 * SCALE, h0, l0); bsplit1(y3 * SCALE, h1, l1);
                    *reinterpret_cast<uint32_t*>(QFH + (size_t)(row0 + 8) * 128 + col) = pack2(h0, h1);
                    *reinterpret_cast<uint32_t*>(QFL + (size_t)(row0 + 8) * 128 + col) = pack2(l0, l1);
                } else {
                    *reinterpret_cast<float2*>(&Yk[(size_t)row0 * 128 + col])       = make_float2(y0, y1);
                    *reinterpret_cast<float2*>(&Yk[(size_t)(row0 + 8) * 128 + col]) = make_float2(y2, y3);
                }
            }
    }
}

// ---------------- phase A: intra-chunk attention + KV via HMMA bf16 3-pass ---
#define AQROW 272
#define ATROW 144
#define A_oQh 0
#define A_oQl 17408
#define A_oKh 34816
#define A_oKl 52224
#define A_oKTh 69632
#define A_oKTl 88064
#define A_oVTh 106496
#define A_oVTl 124928
#define A_oSh  143360
#define A_oSl  152576
#define ATTN_INTRA_SMEM 161792

__global__ __launch_bounds__(256, 1)
void attn_intra_hmma(const __nv_bfloat16* __restrict__ QH, const __nv_bfloat16* __restrict__ QL,
                     const float* __restrict__ Kf,
                     const float* __restrict__ V,
                     float* __restrict__ O,
                     float* __restrict__ KVb)
{
    extern __shared__ char sm[];
    uint32_t sb = smem_to_u32(sm);
    int c = blockIdx.x, bh = blockIdx.y;
    int b = bh >> 3, h = bh & 7;
    int t0 = c * CHUNKSZ;
    int tid = threadIdx.x, wid = tid >> 5, lane = tid & 31;

    // q: direct uint4 copies (presplit, pre-scaled by fm)
#pragma unroll
    for (int it = 0; it < 4; ++it) {
        int idx = tid + it * 256;
        int m = idx >> 4, c16 = idx & 15;
        size_t r = (size_t)(b * TLEN + t0 + m) * NHEAD + h;
        size_t gsrc = r * 16 + c16;
        uint32_t off = m * AQROW + c16 * 16;
        *reinterpret_cast<uint4*>(sm + A_oQh + off) = reinterpret_cast<const uint4*>(QH)[gsrc];
        *reinterpret_cast<uint4*>(sm + A_oQl + off) = reinterpret_cast<const uint4*>(QL)[gsrc];
    }
    // k, v: load fp32, split, row-major + transposed
#pragma unroll
    for (int it = 0; it < 8; ++it) {
        int idx = tid + it * 256;
        int m = idx & 63, d4 = idx >> 6;
        size_t g = ((size_t)((b * TLEN + t0 + m) * NHEAD) + h) * DKK + d4 * 4;
        __nv_bfloat16 hh[4], ll[4];

        float4 vk = *reinterpret_cast<const float4*>(Kf + g);
        bsplit4a(vk, hh, ll);
        *reinterpret_cast<uint32_t*>(sm + A_oKh + m * AQROW + d4 * 8)     = pack2(hh[0], hh[1]);
        *reinterpret_cast<uint32_t*>(sm + A_oKh + m * AQROW + d4 * 8 + 4) = pack2(hh[2], hh[3]);
        *reinterpret_cast<uint32_t*>(sm + A_oKl + m * AQROW + d4 * 8)     = pack2(ll[0], ll[1]);
        *reinterpret_cast<uint32_t*>(sm + A_oKl + m * AQROW + d4 * 8 + 4) = pack2(ll[2], ll[3]);
#pragma unroll
        for (int j = 0; j < 4; ++j) {
            int d = d4 * 4 + j;
            *reinterpret_cast<__nv_bfloat16*>(sm + A_oKTh + d * ATROW + m * 2) = hh[j];
            *reinterpret_cast<__nv_bfloat16*>(sm + A_oKTl + d * ATROW + m * 2) = ll[j];
        }

        float4 vv = *reinterpret_cast<const float4*>(V + g);
        bsplit4a(vv, hh, ll);
#pragma unroll
        for (int j = 0; j < 4; ++j) {
            int d = d4 * 4 + j;
            *reinterpret_cast<__nv_bfloat16*>(sm + A_oVTh + d * ATROW + m * 2) = hh[j];
            *reinterpret_cast<__nv_bfloat16*>(sm + A_oVTl + d * ATROW + m * 2) = ll[j];
        }
    }
    __syncthreads();

    int bg = lane >> 3;
    int cr = lane >> 2, cc = (lane & 3) * 2;

    // ---- (a) S = q k^T (q pre-scaled), masked, stored hi/lo ----
    {
        int wm = (wid & 3) * 16, wn = (wid >> 2) * 32;
        float accS[4][4];
#pragma unroll
        for (int j = 0; j < 4; ++j)
#pragma unroll
            for (int r = 0; r < 4; ++r) accS[j][r] = 0.f;

        uint32_t aAddr = sb + (wm + (lane & 15)) * AQROW + (lane >> 4) * 16;
        uint32_t bAddr = sb + (wn + ((bg >> 1) * 8) + (lane & 7)) * AQROW + (bg & 1) * 16;
#pragma unroll
        for (int ks = 0; ks < 8; ++ks) {
            uint32_t rah[4], ral[4];
            ldmx4(rah, aAddr + A_oQh + ks * 32);
            ldmx4(ral, aAddr + A_oQl + ks * 32);
            uint32_t rbh[4][2], rbl[4][2];
#pragma unroll
            for (int np = 0; np < 2; ++np) {
                uint32_t t[4];
                ldmx4(t, bAddr + A_oKh + np * 16 * AQROW + ks * 32);
                rbh[np*2][0] = t[0]; rbh[np*2][1] = t[1];
                rbh[np*2+1][0] = t[2]; rbh[np*2+1][1] = t[3];
                ldmx4(t, bAddr + A_oKl + np * 16 * AQROW + ks * 32);
                rbl[np*2][0] = t[0]; rbl[np*2][1] = t[1];
                rbl[np*2+1][0] = t[2]; rbl[np*2+1][1] = t[3];
            }
#pragma unroll
            for (int nt = 0; nt < 4; ++nt) mma16816(accS[nt], rah, rbh[nt]);
#pragma unroll
            for (int nt = 0; nt < 4; ++nt) mma16816(accS[nt], rah, rbl[nt]);
#pragma unroll
            for (int nt = 0; nt < 4; ++nt) mma16816(accS[nt], ral, rbh[nt]);
        }
        int r0 = wm + cr;
#pragma unroll
        for (int nt = 0; nt < 4; ++nt) {
            int c0 = wn + nt * 8 + cc;
            float v00 = (c0     <= r0    ) ? accS[nt][0] : 0.f;
            float v01 = (c0 + 1 <= r0    ) ? accS[nt][1] : 0.f;
            float v10 = (c0     <= r0 + 8) ? accS[nt][2] : 0.f;
            float v11 = (c0 + 1 <= r0 + 8) ? accS[nt][3] : 0.f;
            __nv_bfloat16 h00, l00, h01, l01, h10, l10, h11, l11;
            bsplit1(v00, h00, l00); bsplit1(v01, h01, l01);
            bsplit1(v10, h10, l10); bsplit1(v11, h11, l11);
            *reinterpret_cast<uint32_t*>(sm + A_oSh + r0 * ATROW + c0 * 2)       = pack2(h00, h01);
            *reinterpret_cast<uint32_t*>(sm + A_oSl + r0 * ATROW + c0 * 2)       = pack2(l00, l01);
            *reinterpret_cast<uint32_t*>(sm + A_oSh + (r0 + 8) * ATROW + c0 * 2) = pack2(h10, h11);
            *reinterpret_cast<uint32_t*>(sm + A_oSl + (r0 + 8) * ATROW + c0 * 2) = pack2(l10, l11);
        }
    }

    // ---- (c) KV = k^T v ----
    {
        int wm = (wid & 3) * 32, wn = (wid >> 2) * 64;
        float acc[2][8][4];
#pragma unroll
        for (int i = 0; i < 2; ++i)
#pragma unroll
            for (int j = 0; j < 8; ++j)
#pragma unroll
                for (int r = 0; r < 4; ++r) acc[i][j][r] = 0.f;

        uint32_t aBase = sb + (wm + (lane & 15)) * ATROW + (lane >> 4) * 16;
        uint32_t bBase = sb + (wn + ((bg >> 1) * 8) + (lane & 7)) * ATROW + (bg & 1) * 16;
#pragma unroll
        for (int ks = 0; ks < 4; ++ks) {
            uint32_t rah[2][4], ral[2][4];
#pragma unroll
            for (int mt = 0; mt < 2; ++mt) {
                ldmx4(rah[mt], aBase + A_oKTh + mt * 16 * ATROW + ks * 32);
                ldmx4(ral[mt], aBase + A_oKTl + mt * 16 * ATROW + ks * 32);
            }
            uint32_t rbh[8][2], rbl[8][2];
#pragma unroll
            for (int np = 0; np < 4; ++np) {
                uint32_t t[4];
                ldmx4(t, bBase + A_oVTh + np * 16 * ATROW + ks * 32);
                rbh[np*2][0] = t[0]; rbh[np*2][1] = t[1];
                rbh[np*2+1][0] = t[2]; rbh[np*2+1][1] = t[3];
                ldmx4(t, bBase + A_oVTl + np * 16 * ATROW + ks * 32);
                rbl[np*2][0] = t[0]; rbl[np*2][1] = t[1];
                rbl[np*2+1][0] = t[2]; rbl[np*2+1][1] = t[3];
            }
#pragma unroll
            for (int mt = 0; mt < 2; ++mt)
#pragma unroll
                for (int nt = 0; nt < 8; ++nt) mma16816(acc[mt][nt], rah[mt], rbh[nt]);
#pragma unroll
            for (int mt = 0; mt < 2; ++mt)
#pragma unroll
                for (int nt = 0; nt < 8; ++nt) mma16816(acc[mt][nt], rah[mt], rbl[nt]);
#pragma unroll
            for (int mt = 0; mt < 2; ++mt)
#pragma unroll
                for (int nt = 0; nt < 8; ++nt) mma16816(acc[mt][nt], ral[mt], rbh[nt]);
        }
        float* outp = KVb + ((size_t)bh * NCHUNK + c) * (DKK * DVV);
#pragma unroll
        for (int mt = 0; mt < 2; ++mt)
#pragma unroll
            for (int nt = 0; nt < 8; ++nt) {
                int kd = wm + mt * 16 + cr;
                int vd = wn + nt * 8 + cc;
                *reinterpret_cast<float2*>(&outp[(size_t)kd * 128 + vd]) =
                    make_float2(acc[mt][nt][0], acc[mt][nt][1]);
                *reinterpret_cast<float2*>(&outp[(size_t)(kd + 8) * 128 + vd]) =
                    make_float2(acc[mt][nt][2], acc[mt][nt][3]);
            }
    }
    __syncthreads();

    // ---- (b) O_intra = S_masked · v ----
    {
        int wm = (wid & 3) * 16, wn = (wid >> 2) * 64;
        float acc[8][4];
#pragma unroll
        for (int j = 0; j < 8; ++j)
#pragma unroll
            for (int r = 0; r < 4; ++r) acc[j][r] = 0.f;

        uint32_t aBase = sb + (wm + (lane & 15)) * ATROW + (lane >> 4) * 16;
        uint32_t bBase = sb + (wn + ((bg >> 1) * 8) + (lane & 7)) * ATROW + (bg & 1) * 16;
#pragma unroll
        for (int ks = 0; ks < 4; ++ks) {
            uint32_t rah[4], ral[4];
            ldmx4(rah, aBase + A_oSh + ks * 32);
            ldmx4(ral, aBase + A_oSl + ks * 32);
            uint32_t rbh[8][2], rbl[8][2];
#pragma unroll
            for (int np = 0; np < 4; ++np) {
                uint32_t t[4];
                ldmx4(t, bBase + A_oVTh + np * 16 * ATROW + ks * 32);
                rbh[np*2][0] = t[0]; rbh[np*2][1] = t[1];
                rbh[np*2+1][0] = t[2]; rbh[np*2+1][1] = t[3];
                ldmx4(t, bBase + A_oVTl + np * 16 * ATROW + ks * 32);
                rbl[np*2][0] = t[0]; rbl[np*2][1] = t[1];
                rbl[np*2+1][0] = t[2]; rbl[np*2+1][1] = t[3];
            }
#pragma unroll
            for (int nt = 0; nt < 8; ++nt) mma16816(acc[nt], rah, rbh[nt]);
#pragma unroll
            for (int nt = 0; nt < 8; ++nt) mma16816(acc[nt], rah, rbl[nt]);
#pragma unroll
            for (int nt = 0; nt < 8; ++nt) mma16816(acc[nt], ral, rbh[nt]);
        }
#pragma unroll
        for (int nt = 0; nt < 8; ++nt) {
            int i0 = wm + cr;
            int vd = wn + nt * 8 + cc;
            size_t g0 = ((size_t)((b * TLEN + t0 + i0) * NHEAD) + h) * DVV + vd;
            size_t g1 = ((size_t)((b * TLEN + t0 + i0 + 8) * NHEAD) + h) * DVV + vd;
            *reinterpret_cast<float2*>(&O[g0]) = make_float2(acc[nt][0], acc[nt][1]);
            *reinterpret_cast<float2*>(&O[g1]) = make_float2(acc[nt][2], acc[nt][3]);
        }
    }
}

// ---------------- exclusive prefix scan of KV over chunks -------------------
__global__ void scan_kernel(float* __restrict__ KVb)
{
    int e  = blockIdx.x * 256 + threadIdx.x;
    int bh = blockIdx.y;
    float* base = KVb + (size_t)bh * NCHUNK * DKK * DVV + e;
    float run = 0.f;
#pragma unroll 4
    for (int c = 0; c < NCHUNK; ++c) {
        float v = base[(size_t)c * DKK * DVV];
        base[(size_t)c * DKK * DVV] = run;
        run += v;
    }
}

// ---------------- phase C: O_final = O_intra + q@S, written as bf16 hi/lo ----
#define I_oQh 0
#define I_oQl 17408
#define I_oSTh 34816
#define I_oSTl 69632
#define ATTN_INTER_SMEM 104448

__global__ __launch_bounds__(256, 1)
void attn_inter_hmma(const __nv_bfloat16* __restrict__ QH, const __nv_bfloat16* __restrict__ QL,
                     const float* __restrict__ KVb,
                     const float* __restrict__ O,
                     __nv_bfloat16* __restrict__ OH,
                     __nv_bfloat16* __restrict__ OL)
{
    extern __shared__ char sm[];
    uint32_t sb = smem_to_u32(sm);
    int c = blockIdx.x, bh = blockIdx.y;
    int b = bh >> 3, h = bh & 7;
    int t0 = c * CHUNKSZ;
    int tid = threadIdx.x, wid = tid >> 5, lane = tid & 31;

    // q: direct uint4 copies (presplit, pre-scaled by fm)
#pragma unroll
    for (int it = 0; it < 4; ++it) {
        int idx = tid + it * 256;
        int m = idx >> 4, c16 = idx & 15;
        size_t r = (size_t)(b * TLEN + t0 + m) * NHEAD + h;
        size_t gsrc = r * 16 + c16;
        uint32_t off = m * AQROW + c16 * 16;
        *reinterpret_cast<uint4*>(sm + I_oQh + off) = reinterpret_cast<const uint4*>(QH)[gsrc];
        *reinterpret_cast<uint4*>(sm + I_oQl + off) = reinterpret_cast<const uint4*>(QL)[gsrc];
    }
    const float* Sg = KVb + ((size_t)bh * NCHUNK + c) * (DKK * DVV);
#pragma unroll
    for (int it = 0; it < 16; ++it) {
        int idx = tid + it * 256;
        int kd = idx >> 5, v4 = idx & 31;
        float4 v = *reinterpret_cast<const float4*>(Sg + (size_t)kd * 128 + v4 * 4);
        __nv_bfloat16 hh[4], ll[4];
        bsplit4a(v, hh, ll);
#pragma unroll
        for (int j = 0; j < 4; ++j) {
            int vd = v4 * 4 + j;
            *reinterpret_cast<__nv_bfloat16*>(sm + I_oSTh + vd * AQROW + kd * 2) = hh[j];
            *reinterpret_cast<__nv_bfloat16*>(sm + I_oSTl + vd * AQROW + kd * 2) = ll[j];
        }
    }
    __syncthreads();

    int bg = lane >> 3;
    int wm = (wid & 3) * 16, wn = (wid >> 2) * 64;
    float acc[8][4];
#pragma unroll
    for (int j = 0; j < 8; ++j)
#pragma unroll
        for (int r = 0; r < 4; ++r) acc[j][r] = 0.f;

    uint32_t aBase = sb + (wm + (lane & 15)) * AQROW + (lane >> 4) * 16;
    uint32_t bBase = sb + (wn + ((bg >> 1) * 8) + (lane & 7)) * AQROW + (bg & 1) * 16;
#pragma unroll
    for (int ks = 0; ks < 8; ++ks) {
        uint32_t rah[4], ral[4];
        ldmx4(rah, aBase + I_oQh + ks * 32);
        ldmx4(ral, aBase + I_oQl + ks * 32);
        uint32_t rbh[8][2], rbl[8][2];
#pragma unroll
        for (int np = 0; np < 4; ++np) {
            uint32_t t[4];
            ldmx4(t, bBase + I_oSTh + np * 16 * AQROW + ks * 32);
            rbh[np*2][0] = t[0]; rbh[np*2][1] = t[1];
            rbh[np*2+1][0] = t[2]; rbh[np*2+1][1] = t[3];
            ldmx4(t, bBase + I_oSTl + np * 16 * AQROW + ks * 32);
            rbl[np*2][0] = t[0]; rbl[np*2][1] = t[1];
            rbl[np*2+1][0] = t[2]; rbl[np*2+1][1] = t[3];
        }
#pragma unroll
        for (int nt = 0; nt < 8; ++nt) mma16816(acc[nt], rah, rbh[nt]);
#pragma unroll
        for (int nt = 0; nt < 8; ++nt) mma16816(acc[nt], rah, rbl[nt]);
#pragma unroll
        for (int nt = 0; nt < 8; ++nt) mma16816(acc[nt], ral, rbh[nt]);
    }

    int cr = lane >> 2, cc = (lane & 3) * 2;
#pragma unroll
    for (int nt = 0; nt < 8; ++nt) {
        int i0 = wm + cr;
        int vd = wn + nt * 8 + cc;
        size_t g0 = ((size_t)((b * TLEN + t0 + i0) * NHEAD) + h) * DVV + vd;
        size_t g1 = ((size_t)((b * TLEN + t0 + i0 + 8) * NHEAD) + h) * DVV + vd;
        float2 o0 = *reinterpret_cast<const float2*>(&O[g0]);
        float2 o1 = *reinterpret_cast<const float2*>(&O[g1]);
        o0.x += acc[nt][0]; o0.y += acc[nt][1];
        o1.x += acc[nt][2]; o1.y += acc[nt][3];
        __nv_bfloat16 h0, l0, h1, l1;
        bsplit1(o0.x, h0, l0); bsplit1(o0.y, h1, l1);
        *reinterpret_cast<uint32_t*>(OH + g0) = pack2(h0, h1);
        *reinterpret_cast<uint32_t*>(OL + g0) = pack2(l0, l1);
        bsplit1(o1.x, h0, l0); bsplit1(o1.y, h1, l1);
        *reinterpret_cast<uint32_t*>(OH + g1) = pack2(h0, h1);
        *reinterpret_cast<uint32_t*>(OL + g1) = pack2(l0, l1);
    }
}

// ---------------- launch ----------------------------------------------------
extern "C" void kernel_launch(void* const* d_in, const int* in_sizes, int n_in,
                              void* d_out, int out_size)
{
    const float* x   = (const float*)d_in[0];
    const float* wq  = (const float*)d_in[1];
    const float* wk  = (const float*)d_in[2];
    const float* wv  = (const float*)d_in[3];
    const float* wo  = (const float*)d_in[4];
    const float* cq  = (const float*)d_in[5];
    const float* ck  = (const float*)d_in[6];
    const float* cv  = (const float*)d_in[7];
    const float* q1  = (const float*)d_in[8];
    const float* qb1 = (const float*)d_in[9];
    const float* q2  = (const float*)d_in[10];
    const float* qb2 = (const float*)d_in[11];
    const float* k1  = (const float*)d_in[12];
    const float* kb1 = (const float*)d_in[13];
    const float* k2  = (const float*)d_in[14];
    const float* kb2 = (const float*)d_in[15];
    float* out = (float*)d_out;

    float *qb, *kb, *vb, *qc, *kc, *vc, *qf, *kf, *ob, *kv;
    __nv_bfloat16 *xh, *xl, *wh, *wl, *oh, *ol, *fwh, *fwl;
    cudaGetSymbolAddress((void**)&qb, g_qb);
    cudaGetSymbolAddress((void**)&kb, g_kb);
    cudaGetSymbolAddress((void**)&vb, g_vb);
    cudaGetSymbolAddress((void**)&qc, g_qc);
    cudaGetSymbolAddress((void**)&kc, g_kc);
    cudaGetSymbolAddress((void**)&vc, g_vc);
    cudaGetSymbolAddress((void**)&qf, g_qf);
    cudaGetSymbolAddress((void**)&kf, g_kf);
    cudaGetSymbolAddress((void**)&ob, g_o);
    cudaGetSymbolAddress((void**)&kv, g_kv);
    cudaGetSymbolAddress((void**)&xh, g_xh);
    cudaGetSymbolAddress((void**)&xl, g_xl);
    cudaGetSymbolAddress((void**)&wh, g_wh);
    cudaGetSymbolAddress((void**)&wl, g_wl);
    cudaGetSymbolAddress((void**)&oh, g_oh);
    cudaGetSymbolAddress((void**)&ol, g_ol);
    cudaGetSymbolAddress((void**)&fwh, g_fwh);
    cudaGetSymbolAddress((void**)&fwl, g_fwl);

    // qf buffer reused as presplit scaled bf16 q (hi + lo halves)
    __nv_bfloat16* qfh = (__nv_bfloat16*)qf;
    __nv_bfloat16* qfl = qfh + (size_t)MROWS * HID;

    static int attrs_set = 0;
    if (!attrs_set) {
        cudaFuncSetAttribute(hmma_gemm_qkv, cudaFuncAttributeMaxDynamicSharedMemorySize, GEMM_SMEM);
        cudaFuncSetAttribute(hmma_gemm_wo,  cudaFuncAttributeMaxDynamicSharedMemorySize, GEMM_SMEM);
        cudaFuncSetAttribute(fm_hmma3_kernel, cudaFuncAttributeMaxDynamicSharedMemorySize, FM_SMEM);
        cudaFuncSetAttribute(attn_intra_hmma, cudaFuncAttributeMaxDynamicSharedMemorySize, ATTN_INTRA_SMEM);
        cudaFuncSetAttribute(attn_inter_hmma, cudaFuncAttributeMaxDynamicSharedMemorySize, ATTN_INTER_SMEM);
        attrs_set = 1;
    }

    // conversions (bf16 hi/lo — proven)
    split_kernel<<<MROWS * HID / 4 / 256, 256>>>(x, xh, xl, MROWS * HID / 4);
    split_w_kernel<<<dim3(HH / 4 / 256, 4), 256>>>(wq, wk, wv, wo, wh, wl);
    split_fmw_kernel<<<dim3(16, 4), 256>>>(q1, q2, k1, k2, fwh, fwl);

    // q/k/v projections (R13 pipeline: 4-buffer, 1 barrier, 2-Frag ping-pong)
    hmma_gemm_qkv<<<dim3(HID / 128, MROWS / 128, 3), 512, GEMM_SMEM>>>(xh, xl, wh, wl, qb, kb, vb);

    // conv + silu (merged, fp32 outputs — R13 proven)
    int nconv4 = MROWS * HID / 4 / 256;
    conv_silu4_kernel<<<dim3(nconv4, 3), 256>>>(qb, cq, qc, kb, ck, kc, vb, cv, vc);

    // feature maps (merged q/k; q output pre-scaled bf16 hi/lo)
    fm_hmma3_kernel<<<dim3(FMROWS / 128, 2), 256, FM_SMEM>>>(
        qc, kc, fwh, fwl, qb1, qb2, kb1, kb2, qfh, qfl, kf);

    // attention (bf16 3-pass; q staged via direct copies)
    attn_intra_hmma<<<dim3(NCHUNK, BATCH * NHEAD), 256, ATTN_INTRA_SMEM>>>(qfh, qfl, kf, vc, ob, kv);
    scan_kernel<<<dim3(DKK * DVV / 256, BATCH * NHEAD), 256>>>(kv);
    attn_inter_hmma<<<dim3(NCHUNK, BATCH * NHEAD), 256, ATTN_INTER_SMEM>>>(qfh, qfl, kv, ob, oh, ol);

    // output projection (R13 pipeline)
    hmma_gemm_wo<<<dim3(HID / 128, MROWS / 128), 512, GEMM_SMEM>>>(oh, ol, wh + 3 * (size_t)HH, wl + 3 * (size_t)HH, out);
}